// round 7
// baseline (speedup 1.0000x reference)
#include <cuda_runtime.h>
#include <cuda_fp16.h>
#include <cstdint>

#define NB   8
#define IC   512
#define OC   512
#define PX   4096
#define KTOT 4608
#define NKS  288           // KTOT / 16

// ---------------- scratch (device globals; no allocation) ----------------
__device__ float g_smod[NB * IC];
__device__ float g_s2[NB * IC];
__device__ float g_sig[NB * OC];
__device__ __half g_Ahi[(size_t)NB * OC * KTOT];     // [b][o][k]
__device__ __half g_Alo[(size_t)NB * OC * KTOT];

// ---------------- baseline-PTX helpers (valid on plain sm_103) ----------------
__device__ __forceinline__ void cp16(uint32_t dst, const void* src) {
    asm volatile("cp.async.cg.shared.global [%0], [%1], 16;" :: "r"(dst), "l"(src));
}
__device__ __forceinline__ void cp_commit() {
    asm volatile("cp.async.commit_group;" ::: "memory");
}
__device__ __forceinline__ void cp_wait2() {
    asm volatile("cp.async.wait_group 2;" ::: "memory");
}
__device__ __forceinline__ void ldsm4(uint32_t* r, uint32_t a) {
    asm volatile("ldmatrix.sync.aligned.m8n8.x4.shared.b16 {%0,%1,%2,%3}, [%4];"
                 : "=r"(r[0]), "=r"(r[1]), "=r"(r[2]), "=r"(r[3]) : "r"(a));
}
__device__ __forceinline__ void ldsm4t(uint32_t* r, uint32_t a) {
    asm volatile("ldmatrix.sync.aligned.m8n8.x4.trans.shared.b16 {%0,%1,%2,%3}, [%4];"
                 : "=r"(r[0]), "=r"(r[1]), "=r"(r[2]), "=r"(r[3]) : "r"(a));
}
__device__ __forceinline__ void mma16816(float* c, const uint32_t* a, const uint32_t* b) {
    asm volatile(
        "mma.sync.aligned.m16n8k16.row.col.f32.f16.f16.f32 "
        "{%0,%1,%2,%3},{%4,%5,%6,%7},{%8,%9},{%0,%1,%2,%3};"
        : "+f"(c[0]), "+f"(c[1]), "+f"(c[2]), "+f"(c[3])
        : "r"(a[0]), "r"(a[1]), "r"(a[2]), "r"(a[3]), "r"(b[0]), "r"(b[1]));
}

// ---------------------------------------------------------------------------
// K1: style  s[b,i] = latent.w_lin * C_LIN + b_lin   (warp per output i)
// ---------------------------------------------------------------------------
__global__ void k_style(const float* __restrict__ latent,
                        const float* __restrict__ w_lin,
                        const float* __restrict__ b_lin) {
    __shared__ float lat[512];
    const int b = blockIdx.x;
    const int tid = threadIdx.x, lane = tid & 31;
    lat[tid]       = latent[b * 512 + tid];
    lat[tid + 256] = latent[b * 512 + tid + 256];
    __syncthreads();
    const int i = blockIdx.y * 8 + (tid >> 5);
    const float4* wr = (const float4*)(w_lin + (size_t)i * 512);
    float acc = 0.f;
#pragma unroll
    for (int t = 0; t < 4; ++t) {
        float4 v = __ldg(wr + lane + t * 32);
        int j0 = (lane + t * 32) * 4;
        acc += v.x * lat[j0] + v.y * lat[j0 + 1] + v.z * lat[j0 + 2] + v.w * lat[j0 + 3];
    }
#pragma unroll
    for (int st = 16; st > 0; st >>= 1) acc += __shfl_xor_sync(0xffffffffu, acc, st);
    if (lane == 0) {
        const float C_LIN  = 0.04419417382415922f;   // 1/sqrt(512)
        const float C_CONV = 0.014731391274719742f;  // 1/sqrt(4608)
        float s = acc * C_LIN + b_lin[i];
        g_smod[b * 512 + i] = s * C_CONV;
        g_s2[b * 512 + i]   = s * s;
    }
}

// ---------------------------------------------------------------------------
// K2: sigma_inv[b,o]
// ---------------------------------------------------------------------------
__global__ void k_sigma(const float* __restrict__ w_conv) {
    __shared__ float red[8][128];
    const int o = blockIdx.x;
    const int tid = threadIdx.x;
    float acc[8];
#pragma unroll
    for (int b = 0; b < 8; ++b) acc[b] = 0.f;
    for (int i = tid; i < 512; i += 128) {
        const float* wp = w_conv + ((size_t)o * 512 + i) * 9;
        float ws = 0.f;
#pragma unroll
        for (int t = 0; t < 9; ++t) { float v = wp[t]; ws += v * v; }
#pragma unroll
        for (int b = 0; b < 8; ++b) acc[b] += ws * g_s2[b * 512 + i];
    }
#pragma unroll
    for (int b = 0; b < 8; ++b) red[b][tid] = acc[b];
    __syncthreads();
    for (int st = 64; st > 0; st >>= 1) {
        if (tid < st) {
#pragma unroll
            for (int b = 0; b < 8; ++b) red[b][tid] += red[b][tid + st];
        }
        __syncthreads();
    }
    if (tid < 8) {
        const float C2 = 1.0f / 4608.0f;
        g_sig[tid * 512 + o] = rsqrtf(red[tid][0] * C2 + 1e-8f);
    }
}

// ---------------------------------------------------------------------------
// K3: modulated weights -> fp16 hi/lo planes  [b][o][k]  (16B stores)
// ---------------------------------------------------------------------------
__global__ void k_moda(const float* __restrict__ w_conv) {
    const int o = blockIdx.x, b = blockIdx.y;
    const float* wr = w_conv + (size_t)o * KTOT;
    const float* sm = g_smod + b * IC;
    __half* ah = g_Ahi + ((size_t)(b * OC + o)) * KTOT;
    __half* al = g_Alo + ((size_t)(b * OC + o)) * KTOT;
    for (int g = threadIdx.x; g < KTOT / 8; g += 256) {
        const int k0 = g * 8;
        __half hv[8], lv[8];
#pragma unroll
        for (int e = 0; e < 8; ++e) {
            int k = k0 + e;
            float a = __ldg(wr + k) * sm[k / 9];
            __half hi = __float2half_rn(a);
            hv[e] = hi;
            lv[e] = __float2half_rn(a - __half2float(hi));
        }
        *(uint4*)(ah + k0) = *(const uint4*)hv;
        *(uint4*)(al + k0) = *(const uint4*)lv;
    }
}

// ---------------------------------------------------------------------------
// K4: GEMM with fused + register-pipelined im2col (vectorized x loads).
// BM=128 x BN=256 x BK=16, 512 threads / 16 warps, 2 CTAs/SM.
// A (fp16 hi/lo) via 4-stage cp.async:  A[4][128][40] halfs (hi16|lo16|pad8)
// B built from x, LDG one stage ahead of STS; core 8 px via 2x LDG.128
// (aligned: dx handled by warp-uniform register shift + 1 edge scalar).
// ---------------------------------------------------------------------------
#define A_ST   10240
#define B_ST   8448
#define B_OFF  40960
#define SMEM_TOTAL (B_OFF + 2 * B_ST)   // 57,856

__global__ void __launch_bounds__(512, 2)
k_gemm(const float* __restrict__ x, const float* __restrict__ b_conv,
       float* __restrict__ out) {
    extern __shared__ char smem[];
    const uint32_t sb = (uint32_t)__cvta_generic_to_shared(smem);
    const int tid = threadIdx.x, wid = tid >> 5, lane = tid & 31;
    const int mt = blockIdx.x, nt = blockIdx.y, b = blockIdx.z;
    const int o0 = mt * 128, p0 = nt * 256;
    const int wm = (wid >> 2) * 32, wn = (wid & 3) * 64;

    // -------- A cp.async mapping: 1 cp16/thread --------
    const int arow = tid >> 2, aseg = tid & 3;
    const int apl = aseg >> 1, ahalf = aseg & 1;
    const __half* asrc =
        (apl ? g_Alo : g_Ahi) + ((size_t)(b * OC + o0 + arow)) * KTOT + ahalf * 8;
    const uint32_t adst = sb + (uint32_t)(arow * 80 + apl * 32 + ahalf * 16);

    auto issueA = [&](int s) {
        cp16(adst + (s & 3) * A_ST, asrc + s * 16);
    };

    // -------- fused im2col, register-pipelined, vectorized --------
    const int bkk  = tid >> 5;            // k-row 0..15 == warp id (dx,dy uniform/warp)
    const int bseg = tid & 31;            // 32 px-segments of 8
    const int r0   = p0 >> 6;
    const int lr   = bseg >> 3;           // 0..3 rows within tile
    const int wseg = (bseg & 7) << 3;     // 0..56 (8-aligned)
    const float* xb = x + ((size_t)b * IC << 12);
    const uint32_t bsts = sb + B_OFF + (uint32_t)(bkk * 264 + bseg * 8) * 2;

    float bv[8];                           // stage s+1 data, loaded in iter s-1

    auto loadB = [&](int s) {
        const int k = s * 16 + bkk;
        const int ci = k / 9;
        const int t  = k - ci * 9;
        const int dy = t / 3 - 1;
        const int dx = t - (t / 3) * 3 - 1;   // warp-uniform
        const int h  = r0 + lr + dy;
        if ((unsigned)h < 64u) {
            const float* row = xb + ((size_t)ci << 12) + (h << 6) + wseg;
            float4 c0 = *(const float4*)(row);
            float4 c1 = *(const float4*)(row + 4);
            float core[8] = {c0.x, c0.y, c0.z, c0.w, c1.x, c1.y, c1.z, c1.w};
            if (dx == 0) {
#pragma unroll
                for (int e = 0; e < 8; ++e) bv[e] = core[e];
            } else if (dx < 0) {
                float edge = (wseg > 0) ? __ldg(row - 1) : 0.f;
                bv[0] = edge;
#pragma unroll
                for (int e = 1; e < 8; ++e) bv[e] = core[e - 1];
            } else {
                float edge = (wseg < 56) ? __ldg(row + 8) : 0.f;
#pragma unroll
                for (int e = 0; e < 7; ++e) bv[e] = core[e + 1];
                bv[7] = edge;
            }
        } else {
#pragma unroll
            for (int e = 0; e < 8; ++e) bv[e] = 0.f;
        }
    };
    auto stsB = [&](int buf) {
        __half2 hv[4];
#pragma unroll
        for (int q = 0; q < 4; ++q) hv[q] = __floats2half2_rn(bv[2 * q], bv[2 * q + 1]);
        *(uint4*)((char*)smem + (bsts - sb) + buf * B_ST) = *(const uint4*)hv;
    };

    // -------- ldmatrix lane offsets --------
    const uint32_t a_lane = (uint32_t)((lane & 15) * 80 + (lane >> 4) * 16);
    const uint32_t b_lane = (uint32_t)((((lane & 7) + ((lane >> 3) & 1) * 8) * 264 +
                                       ((lane >> 4) << 3)) * 2);

    float acc[2][8][4];
#pragma unroll
    for (int mi = 0; mi < 2; ++mi)
#pragma unroll
        for (int j = 0; j < 8; ++j)
#pragma unroll
            for (int q = 0; q < 4; ++q) acc[mi][j][q] = 0.f;

    issueA(0); cp_commit();
    issueA(1); cp_commit();
    issueA(2); cp_commit();
    loadB(0); stsB(0);                     // stage 0 -> buf 0
    loadB(1);                              // stage 1 -> bv

#pragma unroll 1
    for (int s = 0; s < NKS; ++s) {
        cp_wait2();
        __syncthreads();
        if (s + 1 < NKS) stsB((s + 1) & 1);   // bv = stage s+1 (LDG landed)
        if (s + 3 < NKS) issueA(s + 3);
        cp_commit();
        if (s + 2 < NKS) loadB(s + 2);        // hidden by stage-s MMAs

        const uint32_t ab = sb + (s & 3) * A_ST;
        const uint32_t bb = sb + B_OFF + (s & 1) * B_ST;

        uint32_t ahi[2][4], alo[2][4];
#pragma unroll
        for (int mi = 0; mi < 2; ++mi) {
            uint32_t ad = ab + (uint32_t)((wm + mi * 16) * 80) + a_lane;
            ldsm4(ahi[mi], ad);
            ldsm4(alo[mi], ad + 32);
        }
#pragma unroll
        for (int n2 = 0; n2 < 4; ++n2) {
            uint32_t bf[4];
            ldsm4t(bf, bb + (uint32_t)((wn + n2 * 16) * 2) + b_lane);
#pragma unroll
            for (int mi = 0; mi < 2; ++mi)
#pragma unroll
                for (int nf = 0; nf < 2; ++nf) {
                    float* c = acc[mi][n2 * 2 + nf];
                    mma16816(c, ahi[mi], &bf[nf * 2]);
                    mma16816(c, alo[mi], &bf[nf * 2]);
                }
        }
    }

    // -------- epilogue: demodulate + bias --------
    const int row_l = lane >> 2, col_l = (lane & 3) * 2;
#pragma unroll
    for (int mi = 0; mi < 2; ++mi) {
        const int oa = o0 + wm + mi * 16 + row_l;
        const int ob = oa + 8;
        const float sa = g_sig[b * OC + oa], ba = b_conv[oa];
        const float sc = g_sig[b * OC + ob], bc = b_conv[ob];
        float* ra = out + (((size_t)(b * OC + oa)) << 12) + p0 + wn + col_l;
        float* rb = out + (((size_t)(b * OC + ob)) << 12) + p0 + wn + col_l;
#pragma unroll
        for (int j = 0; j < 8; ++j) {
            float2 v0, v1;
            v0.x = acc[mi][j][0] * sa + ba;
            v0.y = acc[mi][j][1] * sa + ba;
            v1.x = acc[mi][j][2] * sc + bc;
            v1.y = acc[mi][j][3] * sc + bc;
            *(float2*)(ra + j * 8) = v0;
            *(float2*)(rb + j * 8) = v1;
        }
    }
}

// ---------------------------------------------------------------------------
extern "C" void kernel_launch(void* const* d_in, const int* in_sizes, int n_in,
                              void* d_out, int out_size) {
    const float* x      = (const float*)d_in[0];
    const float* latent = (const float*)d_in[1];
    const float* w_lin  = (const float*)d_in[2];
    const float* b_lin  = (const float*)d_in[3];
    const float* w_conv = (const float*)d_in[4];
    const float* b_conv = (const float*)d_in[5];
    float* out = (float*)d_out;

    cudaFuncSetAttribute(k_gemm, cudaFuncAttributeMaxDynamicSharedMemorySize, SMEM_TOTAL);

    k_style<<<dim3(NB, 64), 256>>>(latent, w_lin, b_lin);
    k_sigma<<<OC, 128>>>(w_conv);
    k_moda<<<dim3(OC, NB), 256>>>(w_conv);
    k_gemm<<<dim3(4, 16, NB), 512, SMEM_TOTAL>>>(x, b_conv, out);
}

// round 8
// speedup vs baseline: 1.5317x; 1.5317x over previous
#include <cuda_runtime.h>
#include <cuda_fp16.h>
#include <cstdint>

#define NB   8
#define IC   512
#define OC   512
#define PX   4096
#define KTOT 4608
#define NKS  288           // KTOT / 16

// ---------------- scratch (device globals; no allocation) ----------------
__device__ float g_smod[NB * IC];
__device__ float g_s2[NB * IC];
__device__ float g_sig[NB * OC];
__device__ __half g_Ahi[(size_t)NB * OC * KTOT];     // [b][o][k]
__device__ __half g_Alo[(size_t)NB * OC * KTOT];

// ---------------- baseline-PTX helpers (valid on plain sm_103) ----------------
__device__ __forceinline__ void cp16(uint32_t dst, const void* src) {
    asm volatile("cp.async.cg.shared.global [%0], [%1], 16;" :: "r"(dst), "l"(src));
}
__device__ __forceinline__ void cp_commit() {
    asm volatile("cp.async.commit_group;" ::: "memory");
}
__device__ __forceinline__ void cp_wait2() {
    asm volatile("cp.async.wait_group 2;" ::: "memory");
}
__device__ __forceinline__ void ldsm4(uint32_t* r, uint32_t a) {
    asm volatile("ldmatrix.sync.aligned.m8n8.x4.shared.b16 {%0,%1,%2,%3}, [%4];"
                 : "=r"(r[0]), "=r"(r[1]), "=r"(r[2]), "=r"(r[3]) : "r"(a));
}
__device__ __forceinline__ void ldsm4t(uint32_t* r, uint32_t a) {
    asm volatile("ldmatrix.sync.aligned.m8n8.x4.trans.shared.b16 {%0,%1,%2,%3}, [%4];"
                 : "=r"(r[0]), "=r"(r[1]), "=r"(r[2]), "=r"(r[3]) : "r"(a));
}
__device__ __forceinline__ void mma16816(float* c, const uint32_t* a, const uint32_t* b) {
    asm volatile(
        "mma.sync.aligned.m16n8k16.row.col.f32.f16.f16.f32 "
        "{%0,%1,%2,%3},{%4,%5,%6,%7},{%8,%9},{%0,%1,%2,%3};"
        : "+f"(c[0]), "+f"(c[1]), "+f"(c[2]), "+f"(c[3])
        : "r"(a[0]), "r"(a[1]), "r"(a[2]), "r"(a[3]), "r"(b[0]), "r"(b[1]));
}

// ---------------------------------------------------------------------------
// K1: style  s[b,i] = latent.w_lin * C_LIN + b_lin   (warp per output i)
// ---------------------------------------------------------------------------
__global__ void k_style(const float* __restrict__ latent,
                        const float* __restrict__ w_lin,
                        const float* __restrict__ b_lin) {
    __shared__ float lat[512];
    const int b = blockIdx.x;
    const int tid = threadIdx.x, lane = tid & 31;
    lat[tid]       = latent[b * 512 + tid];
    lat[tid + 256] = latent[b * 512 + tid + 256];
    __syncthreads();
    const int i = blockIdx.y * 8 + (tid >> 5);
    const float4* wr = (const float4*)(w_lin + (size_t)i * 512);
    float acc = 0.f;
#pragma unroll
    for (int t = 0; t < 4; ++t) {
        float4 v = __ldg(wr + lane + t * 32);
        int j0 = (lane + t * 32) * 4;
        acc += v.x * lat[j0] + v.y * lat[j0 + 1] + v.z * lat[j0 + 2] + v.w * lat[j0 + 3];
    }
#pragma unroll
    for (int st = 16; st > 0; st >>= 1) acc += __shfl_xor_sync(0xffffffffu, acc, st);
    if (lane == 0) {
        const float C_LIN  = 0.04419417382415922f;   // 1/sqrt(512)
        const float C_CONV = 0.014731391274719742f;  // 1/sqrt(4608)
        float s = acc * C_LIN + b_lin[i];
        g_smod[b * 512 + i] = s * C_CONV;
        g_s2[b * 512 + i]   = s * s;
    }
}

// ---------------------------------------------------------------------------
// K2: sigma_inv[b,o]
// ---------------------------------------------------------------------------
__global__ void k_sigma(const float* __restrict__ w_conv) {
    __shared__ float red[8][128];
    const int o = blockIdx.x;
    const int tid = threadIdx.x;
    float acc[8];
#pragma unroll
    for (int b = 0; b < 8; ++b) acc[b] = 0.f;
    for (int i = tid; i < 512; i += 128) {
        const float* wp = w_conv + ((size_t)o * 512 + i) * 9;
        float ws = 0.f;
#pragma unroll
        for (int t = 0; t < 9; ++t) { float v = wp[t]; ws += v * v; }
#pragma unroll
        for (int b = 0; b < 8; ++b) acc[b] += ws * g_s2[b * 512 + i];
    }
#pragma unroll
    for (int b = 0; b < 8; ++b) red[b][tid] = acc[b];
    __syncthreads();
    for (int st = 64; st > 0; st >>= 1) {
        if (tid < st) {
#pragma unroll
            for (int b = 0; b < 8; ++b) red[b][tid] += red[b][tid + st];
        }
        __syncthreads();
    }
    if (tid < 8) {
        const float C2 = 1.0f / 4608.0f;
        g_sig[tid * 512 + o] = rsqrtf(red[tid][0] * C2 + 1e-8f);
    }
}

// ---------------------------------------------------------------------------
// K3: modulated weights -> fp16 hi/lo planes  [b][o][k]  (16B stores)
// ---------------------------------------------------------------------------
__global__ void k_moda(const float* __restrict__ w_conv) {
    const int o = blockIdx.x, b = blockIdx.y;
    const float* wr = w_conv + (size_t)o * KTOT;
    const float* sm = g_smod + b * IC;
    __half* ah = g_Ahi + ((size_t)(b * OC + o)) * KTOT;
    __half* al = g_Alo + ((size_t)(b * OC + o)) * KTOT;
    for (int g = threadIdx.x; g < KTOT / 8; g += 256) {
        const int k0 = g * 8;
        __half hv[8], lv[8];
#pragma unroll
        for (int e = 0; e < 8; ++e) {
            int k = k0 + e;
            float a = __ldg(wr + k) * sm[k / 9];
            __half hi = __float2half_rn(a);
            hv[e] = hi;
            lv[e] = __float2half_rn(a - __half2float(hi));
        }
        *(uint4*)(ah + k0) = *(const uint4*)hv;
        *(uint4*)(al + k0) = *(const uint4*)lv;
    }
}

// ---------------------------------------------------------------------------
// K4: GEMM with fused + register-pipelined im2col (vectorized x loads).
// BM=128 x BN=256 x BK=16, 512 threads / 16 warps, 1 CTA/SM (regs ~126 —
// 2 CTAs/SM forces a 64-reg cap and catastrophic spills; do NOT re-attempt).
// A (fp16 hi/lo) via 4-stage cp.async:  A[4][128][40] halfs (hi16|lo16|pad8)
// B built from x, LDG one stage ahead of STS; core 8 px via 2x LDG.128
// (aligned; warp-uniform dx handled by register shift + 1 edge scalar).
// ---------------------------------------------------------------------------
#define A_ST   10240
#define B_ST   8448
#define B_OFF  40960
#define SMEM_TOTAL (B_OFF + 2 * B_ST)   // 57,856

__global__ void __launch_bounds__(512, 1)
k_gemm(const float* __restrict__ x, const float* __restrict__ b_conv,
       float* __restrict__ out) {
    extern __shared__ char smem[];
    const uint32_t sb = (uint32_t)__cvta_generic_to_shared(smem);
    const int tid = threadIdx.x, wid = tid >> 5, lane = tid & 31;
    const int mt = blockIdx.x, nt = blockIdx.y, b = blockIdx.z;
    const int o0 = mt * 128, p0 = nt * 256;
    const int wm = (wid >> 2) * 32, wn = (wid & 3) * 64;

    // -------- A cp.async mapping: 1 cp16/thread --------
    const int arow = tid >> 2, aseg = tid & 3;
    const int apl = aseg >> 1, ahalf = aseg & 1;
    const __half* asrc =
        (apl ? g_Alo : g_Ahi) + ((size_t)(b * OC + o0 + arow)) * KTOT + ahalf * 8;
    const uint32_t adst = sb + (uint32_t)(arow * 80 + apl * 32 + ahalf * 16);

    auto issueA = [&](int s) {
        cp16(adst + (s & 3) * A_ST, asrc + s * 16);
    };

    // -------- fused im2col, register-pipelined, vectorized --------
    const int bkk  = tid >> 5;            // k-row 0..15 == warp id (dx,dy uniform/warp)
    const int bseg = tid & 31;            // 32 px-segments of 8
    const int r0   = p0 >> 6;
    const int lr   = bseg >> 3;           // 0..3 rows within tile
    const int wseg = (bseg & 7) << 3;     // 0..56 (8-aligned)
    const float* xb = x + ((size_t)b * IC << 12);
    const uint32_t bsts = sb + B_OFF + (uint32_t)(bkk * 264 + bseg * 8) * 2;

    float bv[8];                           // stage s+1 data, loaded in iter s-1

    auto loadB = [&](int s) {
        const int k = s * 16 + bkk;
        const int ci = k / 9;
        const int t  = k - ci * 9;
        const int dy = t / 3 - 1;
        const int dx = t - (t / 3) * 3 - 1;   // warp-uniform
        const int h  = r0 + lr + dy;
        if ((unsigned)h < 64u) {
            const float* row = xb + ((size_t)ci << 12) + (h << 6) + wseg;
            float4 c0 = *(const float4*)(row);
            float4 c1 = *(const float4*)(row + 4);
            float core[8] = {c0.x, c0.y, c0.z, c0.w, c1.x, c1.y, c1.z, c1.w};
            if (dx == 0) {
#pragma unroll
                for (int e = 0; e < 8; ++e) bv[e] = core[e];
            } else if (dx < 0) {
                float edge = (wseg > 0) ? __ldg(row - 1) : 0.f;
                bv[0] = edge;
#pragma unroll
                for (int e = 1; e < 8; ++e) bv[e] = core[e - 1];
            } else {
                float edge = (wseg < 56) ? __ldg(row + 8) : 0.f;
#pragma unroll
                for (int e = 0; e < 7; ++e) bv[e] = core[e + 1];
                bv[7] = edge;
            }
        } else {
#pragma unroll
            for (int e = 0; e < 8; ++e) bv[e] = 0.f;
        }
    };
    auto stsB = [&](int buf) {
        __half2 hv[4];
#pragma unroll
        for (int q = 0; q < 4; ++q) hv[q] = __floats2half2_rn(bv[2 * q], bv[2 * q + 1]);
        *(uint4*)((char*)smem + (bsts - sb) + buf * B_ST) = *(const uint4*)hv;
    };

    // -------- ldmatrix lane offsets --------
    const uint32_t a_lane = (uint32_t)((lane & 15) * 80 + (lane >> 4) * 16);
    const uint32_t b_lane = (uint32_t)((((lane & 7) + ((lane >> 3) & 1) * 8) * 264 +
                                       ((lane >> 4) << 3)) * 2);

    float acc[2][8][4];
#pragma unroll
    for (int mi = 0; mi < 2; ++mi)
#pragma unroll
        for (int j = 0; j < 8; ++j)
#pragma unroll
            for (int q = 0; q < 4; ++q) acc[mi][j][q] = 0.f;

    issueA(0); cp_commit();
    issueA(1); cp_commit();
    issueA(2); cp_commit();
    loadB(0); stsB(0);                     // stage 0 -> buf 0
    loadB(1);                              // stage 1 -> bv

#pragma unroll 1
    for (int s = 0; s < NKS; ++s) {
        cp_wait2();
        __syncthreads();
        if (s + 1 < NKS) stsB((s + 1) & 1);   // bv = stage s+1 (LDG landed)
        if (s + 3 < NKS) issueA(s + 3);
        cp_commit();
        if (s + 2 < NKS) loadB(s + 2);        // hidden by stage-s MMAs

        const uint32_t ab = sb + (s & 3) * A_ST;
        const uint32_t bb = sb + B_OFF + (s & 1) * B_ST;

        uint32_t ahi[2][4], alo[2][4];
#pragma unroll
        for (int mi = 0; mi < 2; ++mi) {
            uint32_t ad = ab + (uint32_t)((wm + mi * 16) * 80) + a_lane;
            ldsm4(ahi[mi], ad);
            ldsm4(alo[mi], ad + 32);
        }
#pragma unroll
        for (int n2 = 0; n2 < 4; ++n2) {
            uint32_t bf[4];
            ldsm4t(bf, bb + (uint32_t)((wn + n2 * 16) * 2) + b_lane);
#pragma unroll
            for (int mi = 0; mi < 2; ++mi)
#pragma unroll
                for (int nf = 0; nf < 2; ++nf) {
                    float* c = acc[mi][n2 * 2 + nf];
                    mma16816(c, ahi[mi], &bf[nf * 2]);
                    mma16816(c, alo[mi], &bf[nf * 2]);
                }
        }
    }

    // -------- epilogue: demodulate + bias --------
    const int row_l = lane >> 2, col_l = (lane & 3) * 2;
#pragma unroll
    for (int mi = 0; mi < 2; ++mi) {
        const int oa = o0 + wm + mi * 16 + row_l;
        const int ob = oa + 8;
        const float sa = g_sig[b * OC + oa], ba = b_conv[oa];
        const float sc = g_sig[b * OC + ob], bc = b_conv[ob];
        float* ra = out + (((size_t)(b * OC + oa)) << 12) + p0 + wn + col_l;
        float* rb = out + (((size_t)(b * OC + ob)) << 12) + p0 + wn + col_l;
#pragma unroll
        for (int j = 0; j < 8; ++j) {
            float2 v0, v1;
            v0.x = acc[mi][j][0] * sa + ba;
            v0.y = acc[mi][j][1] * sa + ba;
            v1.x = acc[mi][j][2] * sc + bc;
            v1.y = acc[mi][j][3] * sc + bc;
            *(float2*)(ra + j * 8) = v0;
            *(float2*)(rb + j * 8) = v1;
        }
    }
}

// ---------------------------------------------------------------------------
extern "C" void kernel_launch(void* const* d_in, const int* in_sizes, int n_in,
                              void* d_out, int out_size) {
    const float* x      = (const float*)d_in[0];
    const float* latent = (const float*)d_in[1];
    const float* w_lin  = (const float*)d_in[2];
    const float* b_lin  = (const float*)d_in[3];
    const float* w_conv = (const float*)d_in[4];
    const float* b_conv = (const float*)d_in[5];
    float* out = (float*)d_out;

    cudaFuncSetAttribute(k_gemm, cudaFuncAttributeMaxDynamicSharedMemorySize, SMEM_TOTAL);

    k_style<<<dim3(NB, 64), 256>>>(latent, w_lin, b_lin);
    k_sigma<<<OC, 128>>>(w_conv);
    k_moda<<<dim3(OC, NB), 256>>>(w_conv);
    k_gemm<<<dim3(4, 16, NB), 512, SMEM_TOTAL>>>(x, b_conv, out);
}

// round 10
// speedup vs baseline: 2.8560x; 1.8645x over previous
#include <cuda_runtime.h>
#include <cuda_fp16.h>
#include <cstdint>

#define NB   8
#define IC   512
#define OC   512
#define PX   4096
#define KTOT 4608
#define NKS  288           // KTOT / 16

// ---------------- scratch (device globals; no allocation) ----------------
__device__ float g_smod[NB * IC];
__device__ float g_s2[NB * IC];
__device__ float g_sig[NB * OC];
__device__ __half g_Ahi[(size_t)NB * OC * KTOT];     // [b][o][k]
__device__ __half g_Alo[(size_t)NB * OC * KTOT];

// ---------------- baseline-PTX helpers (valid on plain sm_103) ----------------
__device__ __forceinline__ void cp16(uint32_t dst, const void* src) {
    asm volatile("cp.async.cg.shared.global [%0], [%1], 16;" :: "r"(dst), "l"(src));
}
__device__ __forceinline__ void cp_commit() {
    asm volatile("cp.async.commit_group;" ::: "memory");
}
__device__ __forceinline__ void cp_wait2() {
    asm volatile("cp.async.wait_group 2;" ::: "memory");
}
__device__ __forceinline__ void ldsm4(uint32_t* r, uint32_t a) {
    asm volatile("ldmatrix.sync.aligned.m8n8.x4.shared.b16 {%0,%1,%2,%3}, [%4];"
                 : "=r"(r[0]), "=r"(r[1]), "=r"(r[2]), "=r"(r[3]) : "r"(a));
}
__device__ __forceinline__ void ldsm4t(uint32_t* r, uint32_t a) {
    asm volatile("ldmatrix.sync.aligned.m8n8.x4.trans.shared.b16 {%0,%1,%2,%3}, [%4];"
                 : "=r"(r[0]), "=r"(r[1]), "=r"(r[2]), "=r"(r[3]) : "r"(a));
}
__device__ __forceinline__ void mma16816(float* c, const uint32_t* a, const uint32_t* b) {
    asm volatile(
        "mma.sync.aligned.m16n8k16.row.col.f32.f16.f16.f32 "
        "{%0,%1,%2,%3},{%4,%5,%6,%7},{%8,%9},{%0,%1,%2,%3};"
        : "+f"(c[0]), "+f"(c[1]), "+f"(c[2]), "+f"(c[3])
        : "r"(a[0]), "r"(a[1]), "r"(a[2]), "r"(a[3]), "r"(b[0]), "r"(b[1]));
}

// ---------------------------------------------------------------------------
// K1: style  s[b,i] = latent.w_lin * C_LIN + b_lin   (warp per output i)
// ---------------------------------------------------------------------------
__global__ void k_style(const float* __restrict__ latent,
                        const float* __restrict__ w_lin,
                        const float* __restrict__ b_lin) {
    __shared__ float lat[512];
    const int b = blockIdx.x;
    const int tid = threadIdx.x, lane = tid & 31;
    lat[tid]       = latent[b * 512 + tid];
    lat[tid + 256] = latent[b * 512 + tid + 256];
    __syncthreads();
    const int i = blockIdx.y * 8 + (tid >> 5);
    const float4* wr = (const float4*)(w_lin + (size_t)i * 512);
    float acc = 0.f;
#pragma unroll
    for (int t = 0; t < 4; ++t) {
        float4 v = __ldg(wr + lane + t * 32);
        int j0 = (lane + t * 32) * 4;
        acc += v.x * lat[j0] + v.y * lat[j0 + 1] + v.z * lat[j0 + 2] + v.w * lat[j0 + 3];
    }
#pragma unroll
    for (int st = 16; st > 0; st >>= 1) acc += __shfl_xor_sync(0xffffffffu, acc, st);
    if (lane == 0) {
        const float C_LIN  = 0.04419417382415922f;   // 1/sqrt(512)
        const float C_CONV = 0.014731391274719742f;  // 1/sqrt(4608)
        float s = acc * C_LIN + b_lin[i];
        g_smod[b * 512 + i] = s * C_CONV;
        g_s2[b * 512 + i]   = s * s;
    }
}

// ---------------------------------------------------------------------------
// K2: sigma_inv[b,o]
// ---------------------------------------------------------------------------
__global__ void k_sigma(const float* __restrict__ w_conv) {
    __shared__ float red[8][128];
    const int o = blockIdx.x;
    const int tid = threadIdx.x;
    float acc[8];
#pragma unroll
    for (int b = 0; b < 8; ++b) acc[b] = 0.f;
    for (int i = tid; i < 512; i += 128) {
        const float* wp = w_conv + ((size_t)o * 512 + i) * 9;
        float ws = 0.f;
#pragma unroll
        for (int t = 0; t < 9; ++t) { float v = wp[t]; ws += v * v; }
#pragma unroll
        for (int b = 0; b < 8; ++b) acc[b] += ws * g_s2[b * 512 + i];
    }
#pragma unroll
    for (int b = 0; b < 8; ++b) red[b][tid] = acc[b];
    __syncthreads();
    for (int st = 64; st > 0; st >>= 1) {
        if (tid < st) {
#pragma unroll
            for (int b = 0; b < 8; ++b) red[b][tid] += red[b][tid + st];
        }
        __syncthreads();
    }
    if (tid < 8) {
        const float C2 = 1.0f / 4608.0f;
        g_sig[tid * 512 + o] = rsqrtf(red[tid][0] * C2 + 1e-8f);
    }
}

// ---------------------------------------------------------------------------
// K3: modulated weights -> fp16 hi/lo planes  [b][o][k]  (16B stores)
// ---------------------------------------------------------------------------
__global__ void k_moda(const float* __restrict__ w_conv) {
    const int o = blockIdx.x, b = blockIdx.y;
    const float* wr = w_conv + (size_t)o * KTOT;
    const float* sm = g_smod + b * IC;
    __half* ah = g_Ahi + ((size_t)(b * OC + o)) * KTOT;
    __half* al = g_Alo + ((size_t)(b * OC + o)) * KTOT;
    for (int g = threadIdx.x; g < KTOT / 8; g += 256) {
        const int k0 = g * 8;
        __half hv[8], lv[8];
#pragma unroll
        for (int e = 0; e < 8; ++e) {
            int k = k0 + e;
            float a = __ldg(wr + k) * sm[k / 9];
            __half hi = __float2half_rn(a);
            hv[e] = hi;
            lv[e] = __float2half_rn(a - __half2float(hi));
        }
        *(uint4*)(ah + k0) = *(const uint4*)hv;
        *(uint4*)(al + k0) = *(const uint4*)lv;
    }
}

// ---------------------------------------------------------------------------
// K4: GEMM with fused + register-pipelined im2col.
// BM=128 x BN=256 x BK=16, 512 threads / 16 warps, 1 CTA/SM (regs ~126 —
// 2 CTAs/SM forces a 64-reg cap and catastrophic spills; do NOT re-attempt).
// B build: lane-contiguous px mapping (px = e*32 + lane) so every LDG is a
// warp-contiguous 128B access, fully predicated / branch-free so the
// one-stage-ahead prefetch stays hoistable (branchy loadB regressed: R8).
// ---------------------------------------------------------------------------
#define A_ST   10240
#define B_ST   8448
#define B_OFF  40960
#define SMEM_TOTAL (B_OFF + 2 * B_ST)   // 57,856

__global__ void __launch_bounds__(512, 1)
k_gemm(const float* __restrict__ x, const float* __restrict__ b_conv,
       float* __restrict__ out) {
    extern __shared__ char smem[];
    const uint32_t sb = (uint32_t)__cvta_generic_to_shared(smem);
    const int tid = threadIdx.x, wid = tid >> 5, lane = tid & 31;
    const int mt = blockIdx.x, nt = blockIdx.y, b = blockIdx.z;
    const int o0 = mt * 128, p0 = nt * 256;
    const int wm = (wid >> 2) * 32, wn = (wid & 3) * 64;

    // -------- A cp.async mapping: 1 cp16/thread --------
    const int arow = tid >> 2, aseg = tid & 3;
    const int apl = aseg >> 1, ahalf = aseg & 1;
    const __half* asrc =
        (apl ? g_Alo : g_Ahi) + ((size_t)(b * OC + o0 + arow)) * KTOT + ahalf * 8;
    const uint32_t adst = sb + (uint32_t)(arow * 80 + apl * 32 + ahalf * 16);

    auto issueA = [&](int s) {
        cp16(adst + (s & 3) * A_ST, asrc + s * 16);
    };

    // -------- fused im2col, register-pipelined, coalesced lanes --------
    const int bkk = tid >> 5;             // k-row 0..15 == warp id
    const int r0  = p0 >> 6;              // base image row of this N-tile
    const float* xb = x + ((size_t)b * IC << 12);
    const uint32_t brow = (uint32_t)(B_OFF + bkk * 264 * 2);

    float bv[8];                           // stage s+1 data, loaded in iter s-1

    auto loadB = [&](int s) {              // branch-free, predicated LDGs
        const int k = s * 16 + bkk;
        const int ci = k / 9;
        const int t  = k - ci * 9;
        const int dy = t / 3 - 1;
        const int dx = t - (t / 3) * 3 - 1;
        const float* xc = xb + ((size_t)ci << 12);
#pragma unroll
        for (int e = 0; e < 8; ++e) {
            const int h = r0 + (e >> 1) + dy;             // uniform per e
            const int w = ((e & 1) << 5) + lane + dx;     // lane-contiguous
            bv[e] = ((unsigned)h < 64u && (unsigned)w < 64u)
                        ? __ldg(xc + (h << 6) + w) : 0.f;
        }
    };
    auto stsB = [&](int buf) {             // cvt + 8 scalar half STS (64B/warp)
#pragma unroll
        for (int e = 0; e < 8; ++e) {
            __half hv = __float2half_rn(bv[e]);
            *(__half*)(smem + brow + buf * B_ST +
                       (uint32_t)(((e << 5) + lane) * 2)) = hv;
        }
    };

    // -------- ldmatrix lane offsets --------
    const uint32_t a_lane = (uint32_t)((lane & 15) * 80 + (lane >> 4) * 16);
    const uint32_t b_lane = (uint32_t)((((lane & 7) + ((lane >> 3) & 1) * 8) * 264 +
                                       ((lane >> 4) << 3)) * 2);

    float acc[2][8][4];
#pragma unroll
    for (int mi = 0; mi < 2; ++mi)
#pragma unroll
        for (int j = 0; j < 8; ++j)
#pragma unroll
            for (int q = 0; q < 4; ++q) acc[mi][j][q] = 0.f;

    issueA(0); cp_commit();
    issueA(1); cp_commit();
    issueA(2); cp_commit();
    loadB(0); stsB(0);                     // stage 0 -> buf 0
    loadB(1);                              // stage 1 -> bv

#pragma unroll 1
    for (int s = 0; s < NKS; ++s) {
        cp_wait2();
        __syncthreads();
        if (s + 1 < NKS) stsB((s + 1) & 1);   // bv = stage s+1 (LDG landed)
        if (s + 3 < NKS) issueA(s + 3);
        cp_commit();
        if (s + 2 < NKS) loadB(s + 2);        // hidden by stage-s MMAs

        const uint32_t ab = sb + (s & 3) * A_ST;
        const uint32_t bb = sb + B_OFF + (s & 1) * B_ST;

        uint32_t ahi[2][4], alo[2][4];
#pragma unroll
        for (int mi = 0; mi < 2; ++mi) {
            uint32_t ad = ab + (uint32_t)((wm + mi * 16) * 80) + a_lane;
            ldsm4(ahi[mi], ad);
            ldsm4(alo[mi], ad + 32);
        }
#pragma unroll
        for (int n2 = 0; n2 < 4; ++n2) {
            uint32_t bf[4];
            ldsm4t(bf, bb + (uint32_t)((wn + n2 * 16) * 2) + b_lane);
#pragma unroll
            for (int mi = 0; mi < 2; ++mi)
#pragma unroll
                for (int nf = 0; nf < 2; ++nf) {
                    float* c = acc[mi][n2 * 2 + nf];
                    mma16816(c, ahi[mi], &bf[nf * 2]);
                    mma16816(c, alo[mi], &bf[nf * 2]);
                }
        }
    }

    // -------- epilogue: demodulate + bias --------
    const int row_l = lane >> 2, col_l = (lane & 3) * 2;
#pragma unroll
    for (int mi = 0; mi < 2; ++mi) {
        const int oa = o0 + wm + mi * 16 + row_l;
        const int ob = oa + 8;
        const float sa = g_sig[b * OC + oa], ba = b_conv[oa];
        const float sc = g_sig[b * OC + ob], bc = b_conv[ob];
        float* ra = out + (((size_t)(b * OC + oa)) << 12) + p0 + wn + col_l;
        float* rb = out + (((size_t)(b * OC + ob)) << 12) + p0 + wn + col_l;
#pragma unroll
        for (int j = 0; j < 8; ++j) {
            float2 v0, v1;
            v0.x = acc[mi][j][0] * sa + ba;
            v0.y = acc[mi][j][1] * sa + ba;
            v1.x = acc[mi][j][2] * sc + bc;
            v1.y = acc[mi][j][3] * sc + bc;
            *(float2*)(ra + j * 8) = v0;
            *(float2*)(rb + j * 8) = v1;
        }
    }
}

// ---------------------------------------------------------------------------
extern "C" void kernel_launch(void* const* d_in, const int* in_sizes, int n_in,
                              void* d_out, int out_size) {
    const float* x      = (const float*)d_in[0];
    const float* latent = (const float*)d_in[1];
    const float* w_lin  = (const float*)d_in[2];
    const float* b_lin  = (const float*)d_in[3];
    const float* w_conv = (const float*)d_in[4];
    const float* b_conv = (const float*)d_in[5];
    float* out = (float*)d_out;

    cudaFuncSetAttribute(k_gemm, cudaFuncAttributeMaxDynamicSharedMemorySize, SMEM_TOTAL);

    k_style<<<dim3(NB, 64), 256>>>(latent, w_lin, b_lin);
    k_sigma<<<OC, 128>>>(w_conv);
    k_moda<<<dim3(OC, NB), 256>>>(w_conv);
    k_gemm<<<dim3(4, 16, NB), 512, SMEM_TOTAL>>>(x, b_conv, out);
}

// round 11
// speedup vs baseline: 3.0653x; 1.0733x over previous
#include <cuda_runtime.h>
#include <cuda_fp16.h>
#include <cstdint>

#define NB   8
#define IC   512
#define OC   512
#define PX   4096
#define KTOT 4608
#define NKS  288           // KTOT / 16

// ---------------- scratch (device globals; no allocation) ----------------
__device__ float g_smod[NB * IC];
__device__ float g_s2[NB * IC];
__device__ float g_sig[NB * OC];
__device__ __half g_Ahi[(size_t)NB * OC * KTOT];     // [b][o][k]
__device__ __half g_Alo[(size_t)NB * OC * KTOT];
// shifted, halo-padded fp16 images: [b][shift 0..2][ci][h_pad 0..65][w 0..63]
// value = x[b][ci][h_pad-1][w + (shift-1)] or 0 out of range.  103.8 MB
__device__ __half g_xsh[(size_t)NB * 3 * IC * 66 * 64];

// ---------------- baseline-PTX helpers (valid on plain sm_103) ----------------
__device__ __forceinline__ void cp16(uint32_t dst, const void* src) {
    asm volatile("cp.async.cg.shared.global [%0], [%1], 16;" :: "r"(dst), "l"(src));
}
__device__ __forceinline__ void cp_commit() {
    asm volatile("cp.async.commit_group;" ::: "memory");
}
__device__ __forceinline__ void cp_wait2() {
    asm volatile("cp.async.wait_group 2;" ::: "memory");
}
__device__ __forceinline__ void ldsm4(uint32_t* r, uint32_t a) {
    asm volatile("ldmatrix.sync.aligned.m8n8.x4.shared.b16 {%0,%1,%2,%3}, [%4];"
                 : "=r"(r[0]), "=r"(r[1]), "=r"(r[2]), "=r"(r[3]) : "r"(a));
}
__device__ __forceinline__ void ldsm4t(uint32_t* r, uint32_t a) {
    asm volatile("ldmatrix.sync.aligned.m8n8.x4.trans.shared.b16 {%0,%1,%2,%3}, [%4];"
                 : "=r"(r[0]), "=r"(r[1]), "=r"(r[2]), "=r"(r[3]) : "r"(a));
}
__device__ __forceinline__ void mma16816(float* c, const uint32_t* a, const uint32_t* b) {
    asm volatile(
        "mma.sync.aligned.m16n8k16.row.col.f32.f16.f16.f32 "
        "{%0,%1,%2,%3},{%4,%5,%6,%7},{%8,%9},{%0,%1,%2,%3};"
        : "+f"(c[0]), "+f"(c[1]), "+f"(c[2]), "+f"(c[3])
        : "r"(a[0]), "r"(a[1]), "r"(a[2]), "r"(a[3]), "r"(b[0]), "r"(b[1]));
}

// ---------------------------------------------------------------------------
// K1: style  s[b,i] = latent.w_lin * C_LIN + b_lin   (warp per output i)
// ---------------------------------------------------------------------------
__global__ void k_style(const float* __restrict__ latent,
                        const float* __restrict__ w_lin,
                        const float* __restrict__ b_lin) {
    __shared__ float lat[512];
    const int b = blockIdx.x;
    const int tid = threadIdx.x, lane = tid & 31;
    lat[tid]       = latent[b * 512 + tid];
    lat[tid + 256] = latent[b * 512 + tid + 256];
    __syncthreads();
    const int i = blockIdx.y * 8 + (tid >> 5);
    const float4* wr = (const float4*)(w_lin + (size_t)i * 512);
    float acc = 0.f;
#pragma unroll
    for (int t = 0; t < 4; ++t) {
        float4 v = __ldg(wr + lane + t * 32);
        int j0 = (lane + t * 32) * 4;
        acc += v.x * lat[j0] + v.y * lat[j0 + 1] + v.z * lat[j0 + 2] + v.w * lat[j0 + 3];
    }
#pragma unroll
    for (int st = 16; st > 0; st >>= 1) acc += __shfl_xor_sync(0xffffffffu, acc, st);
    if (lane == 0) {
        const float C_LIN  = 0.04419417382415922f;   // 1/sqrt(512)
        const float C_CONV = 0.014731391274719742f;  // 1/sqrt(4608)
        float s = acc * C_LIN + b_lin[i];
        g_smod[b * 512 + i] = s * C_CONV;
        g_s2[b * 512 + i]   = s * s;
    }
}

// ---------------------------------------------------------------------------
// K2: sigma_inv[b,o]
// ---------------------------------------------------------------------------
__global__ void k_sigma(const float* __restrict__ w_conv) {
    __shared__ float red[8][128];
    const int o = blockIdx.x;
    const int tid = threadIdx.x;
    float acc[8];
#pragma unroll
    for (int b = 0; b < 8; ++b) acc[b] = 0.f;
    for (int i = tid; i < 512; i += 128) {
        const float* wp = w_conv + ((size_t)o * 512 + i) * 9;
        float ws = 0.f;
#pragma unroll
        for (int t = 0; t < 9; ++t) { float v = wp[t]; ws += v * v; }
#pragma unroll
        for (int b = 0; b < 8; ++b) acc[b] += ws * g_s2[b * 512 + i];
    }
#pragma unroll
    for (int b = 0; b < 8; ++b) red[b][tid] = acc[b];
    __syncthreads();
    for (int st = 64; st > 0; st >>= 1) {
        if (tid < st) {
#pragma unroll
            for (int b = 0; b < 8; ++b) red[b][tid] += red[b][tid + st];
        }
        __syncthreads();
    }
    if (tid < 8) {
        const float C2 = 1.0f / 4608.0f;
        g_sig[tid * 512 + o] = rsqrtf(red[tid][0] * C2 + 1e-8f);
    }
}

// ---------------------------------------------------------------------------
// K3: modulated weights -> fp16 hi/lo planes  [b][o][k]  (16B stores)
// ---------------------------------------------------------------------------
__global__ void k_moda(const float* __restrict__ w_conv) {
    const int o = blockIdx.x, b = blockIdx.y;
    const float* wr = w_conv + (size_t)o * KTOT;
    const float* sm = g_smod + b * IC;
    __half* ah = g_Ahi + ((size_t)(b * OC + o)) * KTOT;
    __half* al = g_Alo + ((size_t)(b * OC + o)) * KTOT;
    for (int g = threadIdx.x; g < KTOT / 8; g += 256) {
        const int k0 = g * 8;
        __half hv[8], lv[8];
#pragma unroll
        for (int e = 0; e < 8; ++e) {
            int k = k0 + e;
            float a = __ldg(wr + k) * sm[k / 9];
            __half hi = __float2half_rn(a);
            hv[e] = hi;
            lv[e] = __float2half_rn(a - __half2float(hi));
        }
        *(uint4*)(ah + k0) = *(const uint4*)hv;
        *(uint4*)(al + k0) = *(const uint4*)lv;
    }
}

// ---------------------------------------------------------------------------
// K4: shifted fp16 image planes with halo: g_xsh[b][sh][ci][hp][w]
//     = x[b][ci][hp-1][w+sh-1]  (0 outside)
// ---------------------------------------------------------------------------
__global__ void k_xsh(const float* __restrict__ x) {
    const int ci = blockIdx.x, sh = blockIdx.y, b = blockIdx.z;
    const float* xc = x + ((size_t)(b * IC + ci) << 12);
    __half* dst = g_xsh + ((((size_t)b * 3 + sh) * IC + ci) * 66) * 64;
    const int dx = sh - 1;
    for (int idx = threadIdx.x; idx < 66 * 64; idx += 256) {
        const int hp = idx >> 6, w = idx & 63;
        const int h = hp - 1, ws = w + dx;
        float v = ((unsigned)h < 64u && (unsigned)ws < 64u)
                      ? __ldg(xc + (h << 6) + ws) : 0.f;
        dst[idx] = __float2half_rn(v);
    }
}

// ---------------------------------------------------------------------------
// K5: GEMM, A and B both pure cp.async (B from pre-shifted fp16 planes).
// BM=128 x BN=256 x BK=16, 512 threads / 16 warps, 1 CTA/SM (2 CTAs/SM ->
// 64-reg cap -> catastrophic spills; do NOT re-attempt).
// A[4][128][40] halfs (hi16|lo16|pad8); B[4][16][264] halfs.
// Per thread per stage: 1 cp16 (A) + 1 cp16 (B).
// ---------------------------------------------------------------------------
#define A_ST   10240
#define B_ST   8448
#define B_OFF  40960
#define SMEM_TOTAL (B_OFF + 4 * B_ST)   // 74,752

__global__ void __launch_bounds__(512, 1)
k_gemm(const float* __restrict__ b_conv, float* __restrict__ out) {
    extern __shared__ char smem[];
    const uint32_t sb = (uint32_t)__cvta_generic_to_shared(smem);
    const int tid = threadIdx.x, wid = tid >> 5, lane = tid & 31;
    const int mt = blockIdx.x, nt = blockIdx.y, b = blockIdx.z;
    const int o0 = mt * 128, p0 = nt * 256;
    const int wm = (wid >> 2) * 32, wn = (wid & 3) * 64;

    // -------- A cp.async mapping: 1 cp16/thread --------
    const int arow = tid >> 2, aseg = tid & 3;
    const int apl = aseg >> 1, ahalf = aseg & 1;
    const __half* asrc =
        (apl ? g_Alo : g_Ahi) + ((size_t)(b * OC + o0 + arow)) * KTOT + ahalf * 8;
    const uint32_t adst = sb + (uint32_t)(arow * 80 + apl * 32 + ahalf * 16);

    auto issueA = [&](int s) {
        cp16(adst + (s & 3) * A_ST, asrc + s * 16);
    };

    // -------- B cp.async mapping: 1 cp16/thread from g_xsh --------
    const int bkk = tid >> 5;             // k-row 0..15 == warp id
    const int lr  = lane >> 3;            // 0..3  image row within N-tile
    const int seg = lane & 7;             // 8-half chunk within 64-px row
    const int r0  = p0 >> 6;
    const __half* xshb = g_xsh + ((size_t)b * 3 * IC) * 66 * 64;
    const uint32_t bdst = sb + B_OFF + (uint32_t)(bkk * 264 + lr * 64 + seg * 8) * 2;

    auto issueB = [&](int s) {
        const int k  = s * 16 + bkk;
        const int ci = k / 9;
        const int t  = k - ci * 9;
        const int ty = t / 3;                         // dy + 1
        const int tx = t - ty * 3;                    // dx + 1 (shift index)
        const __half* src = xshb +
            (((size_t)tx * IC + ci) * 66 + (r0 + lr + ty)) * 64 + seg * 8;
        cp16(bdst + (s & 3) * B_ST, src);
    };

    // -------- ldmatrix lane offsets --------
    const uint32_t a_lane = (uint32_t)((lane & 15) * 80 + (lane >> 4) * 16);
    const uint32_t b_lane = (uint32_t)((((lane & 7) + ((lane >> 3) & 1) * 8) * 264 +
                                       ((lane >> 4) << 3)) * 2);

    float acc[2][8][4];
#pragma unroll
    for (int mi = 0; mi < 2; ++mi)
#pragma unroll
        for (int j = 0; j < 8; ++j)
#pragma unroll
            for (int q = 0; q < 4; ++q) acc[mi][j][q] = 0.f;

    issueA(0); issueB(0); cp_commit();
    issueA(1); issueB(1); cp_commit();
    issueA(2); issueB(2); cp_commit();

#pragma unroll 1
    for (int s = 0; s < NKS; ++s) {
        cp_wait2();
        __syncthreads();
        if (s + 3 < NKS) { issueA(s + 3); issueB(s + 3); }
        cp_commit();

        const uint32_t ab = sb + (s & 3) * A_ST;
        const uint32_t bb = sb + B_OFF + (s & 3) * B_ST;

        uint32_t ahi[2][4], alo[2][4];
#pragma unroll
        for (int mi = 0; mi < 2; ++mi) {
            uint32_t ad = ab + (uint32_t)((wm + mi * 16) * 80) + a_lane;
            ldsm4(ahi[mi], ad);
            ldsm4(alo[mi], ad + 32);
        }
#pragma unroll
        for (int n2 = 0; n2 < 4; ++n2) {
            uint32_t bf[4];
            ldsm4t(bf, bb + (uint32_t)((wn + n2 * 16) * 2) + b_lane);
#pragma unroll
            for (int mi = 0; mi < 2; ++mi)
#pragma unroll
                for (int nf = 0; nf < 2; ++nf) {
                    float* c = acc[mi][n2 * 2 + nf];
                    mma16816(c, ahi[mi], &bf[nf * 2]);
                    mma16816(c, alo[mi], &bf[nf * 2]);
                }
        }
    }

    // -------- epilogue: demodulate + bias --------
    const int row_l = lane >> 2, col_l = (lane & 3) * 2;
#pragma unroll
    for (int mi = 0; mi < 2; ++mi) {
        const int oa = o0 + wm + mi * 16 + row_l;
        const int ob = oa + 8;
        const float sa = g_sig[b * OC + oa], ba = b_conv[oa];
        const float sc = g_sig[b * OC + ob], bc = b_conv[ob];
        float* ra = out + (((size_t)(b * OC + oa)) << 12) + p0 + wn + col_l;
        float* rb = out + (((size_t)(b * OC + ob)) << 12) + p0 + wn + col_l;
#pragma unroll
        for (int j = 0; j < 8; ++j) {
            float2 v0, v1;
            v0.x = acc[mi][j][0] * sa + ba;
            v0.y = acc[mi][j][1] * sa + ba;
            v1.x = acc[mi][j][2] * sc + bc;
            v1.y = acc[mi][j][3] * sc + bc;
            *(float2*)(ra + j * 8) = v0;
            *(float2*)(rb + j * 8) = v1;
        }
    }
}

// ---------------------------------------------------------------------------
extern "C" void kernel_launch(void* const* d_in, const int* in_sizes, int n_in,
                              void* d_out, int out_size) {
    const float* x      = (const float*)d_in[0];
    const float* latent = (const float*)d_in[1];
    const float* w_lin  = (const float*)d_in[2];
    const float* b_lin  = (const float*)d_in[3];
    const float* w_conv = (const float*)d_in[4];
    const float* b_conv = (const float*)d_in[5];
    float* out = (float*)d_out;

    cudaFuncSetAttribute(k_gemm, cudaFuncAttributeMaxDynamicSharedMemorySize, SMEM_TOTAL);

    k_style<<<dim3(NB, 64), 256>>>(latent, w_lin, b_lin);
    k_sigma<<<OC, 128>>>(w_conv);
    k_moda<<<dim3(OC, NB), 256>>>(w_conv);
    k_xsh<<<dim3(IC, 3, NB), 256>>>(x);
    k_gemm<<<dim3(4, 16, NB), 512, SMEM_TOTAL>>>(b_conv, out);
}

// round 12
// speedup vs baseline: 3.2139x; 1.0485x over previous
#include <cuda_runtime.h>
#include <cuda_fp16.h>
#include <cstdint>

#define NB   8
#define IC   512
#define OC   512
#define PX   4096
#define KTOT 4608
#define NKS2 144           // KTOT / 32

// ---------------- scratch (device globals; no allocation) ----------------
__device__ float g_smod[NB * IC];
__device__ float g_s2[NB * IC];
__device__ float g_sig[NB * OC];
__device__ __half g_Ahi[(size_t)NB * OC * KTOT];     // [b][o][k]
__device__ __half g_Alo[(size_t)NB * OC * KTOT];
// shifted, halo-padded fp16 images: [b][shift 0..2][ci][h_pad 0..65][w 0..63]
__device__ __half g_xsh[(size_t)NB * 3 * IC * 66 * 64];

// ---------------- baseline-PTX helpers (valid on plain sm_103) ----------------
__device__ __forceinline__ void cp16(uint32_t dst, const void* src) {
    asm volatile("cp.async.cg.shared.global [%0], [%1], 16;" :: "r"(dst), "l"(src));
}
__device__ __forceinline__ void cp_commit() {
    asm volatile("cp.async.commit_group;" ::: "memory");
}
__device__ __forceinline__ void cp_wait2() {
    asm volatile("cp.async.wait_group 2;" ::: "memory");
}
__device__ __forceinline__ void ldsm4(uint32_t* r, uint32_t a) {
    asm volatile("ldmatrix.sync.aligned.m8n8.x4.shared.b16 {%0,%1,%2,%3}, [%4];"
                 : "=r"(r[0]), "=r"(r[1]), "=r"(r[2]), "=r"(r[3]) : "r"(a));
}
__device__ __forceinline__ void ldsm4t(uint32_t* r, uint32_t a) {
    asm volatile("ldmatrix.sync.aligned.m8n8.x4.trans.shared.b16 {%0,%1,%2,%3}, [%4];"
                 : "=r"(r[0]), "=r"(r[1]), "=r"(r[2]), "=r"(r[3]) : "r"(a));
}
__device__ __forceinline__ void mma16816(float* c, const uint32_t* a, const uint32_t* b) {
    asm volatile(
        "mma.sync.aligned.m16n8k16.row.col.f32.f16.f16.f32 "
        "{%0,%1,%2,%3},{%4,%5,%6,%7},{%8,%9},{%0,%1,%2,%3};"
        : "+f"(c[0]), "+f"(c[1]), "+f"(c[2]), "+f"(c[3])
        : "r"(a[0]), "r"(a[1]), "r"(a[2]), "r"(a[3]), "r"(b[0]), "r"(b[1]));
}

// ---------------------------------------------------------------------------
// K1: style  s[b,i] = latent.w_lin * C_LIN + b_lin   (warp per output i)
// ---------------------------------------------------------------------------
__global__ void k_style(const float* __restrict__ latent,
                        const float* __restrict__ w_lin,
                        const float* __restrict__ b_lin) {
    __shared__ float lat[512];
    const int b = blockIdx.x;
    const int tid = threadIdx.x, lane = tid & 31;
    lat[tid]       = latent[b * 512 + tid];
    lat[tid + 256] = latent[b * 512 + tid + 256];
    __syncthreads();
    const int i = blockIdx.y * 8 + (tid >> 5);
    const float4* wr = (const float4*)(w_lin + (size_t)i * 512);
    float acc = 0.f;
#pragma unroll
    for (int t = 0; t < 4; ++t) {
        float4 v = __ldg(wr + lane + t * 32);
        int j0 = (lane + t * 32) * 4;
        acc += v.x * lat[j0] + v.y * lat[j0 + 1] + v.z * lat[j0 + 2] + v.w * lat[j0 + 3];
    }
#pragma unroll
    for (int st = 16; st > 0; st >>= 1) acc += __shfl_xor_sync(0xffffffffu, acc, st);
    if (lane == 0) {
        const float C_LIN  = 0.04419417382415922f;   // 1/sqrt(512)
        const float C_CONV = 0.014731391274719742f;  // 1/sqrt(4608)
        float s = acc * C_LIN + b_lin[i];
        g_smod[b * 512 + i] = s * C_CONV;
        g_s2[b * 512 + i]   = s * s;
    }
}

// ---------------------------------------------------------------------------
// K2: sigma_inv[b,o]
// ---------------------------------------------------------------------------
__global__ void k_sigma(const float* __restrict__ w_conv) {
    __shared__ float red[8][128];
    const int o = blockIdx.x;
    const int tid = threadIdx.x;
    float acc[8];
#pragma unroll
    for (int b = 0; b < 8; ++b) acc[b] = 0.f;
    for (int i = tid; i < 512; i += 128) {
        const float* wp = w_conv + ((size_t)o * 512 + i) * 9;
        float ws = 0.f;
#pragma unroll
        for (int t = 0; t < 9; ++t) { float v = wp[t]; ws += v * v; }
#pragma unroll
        for (int b = 0; b < 8; ++b) acc[b] += ws * g_s2[b * 512 + i];
    }
#pragma unroll
    for (int b = 0; b < 8; ++b) red[b][tid] = acc[b];
    __syncthreads();
    for (int st = 64; st > 0; st >>= 1) {
        if (tid < st) {
#pragma unroll
            for (int b = 0; b < 8; ++b) red[b][tid] += red[b][tid + st];
        }
        __syncthreads();
    }
    if (tid < 8) {
        const float C2 = 1.0f / 4608.0f;
        g_sig[tid * 512 + o] = rsqrtf(red[tid][0] * C2 + 1e-8f);
    }
}

// ---------------------------------------------------------------------------
// K3: modulated weights -> fp16 hi/lo planes  [b][o][k]  (16B stores)
// ---------------------------------------------------------------------------
__global__ void k_moda(const float* __restrict__ w_conv) {
    const int o = blockIdx.x, b = blockIdx.y;
    const float* wr = w_conv + (size_t)o * KTOT;
    const float* sm = g_smod + b * IC;
    __half* ah = g_Ahi + ((size_t)(b * OC + o)) * KTOT;
    __half* al = g_Alo + ((size_t)(b * OC + o)) * KTOT;
    for (int g = threadIdx.x; g < KTOT / 8; g += 256) {
        const int k0 = g * 8;
        __half hv[8], lv[8];
#pragma unroll
        for (int e = 0; e < 8; ++e) {
            int k = k0 + e;
            float a = __ldg(wr + k) * sm[k / 9];
            __half hi = __float2half_rn(a);
            hv[e] = hi;
            lv[e] = __float2half_rn(a - __half2float(hi));
        }
        *(uint4*)(ah + k0) = *(const uint4*)hv;
        *(uint4*)(al + k0) = *(const uint4*)lv;
    }
}

// ---------------------------------------------------------------------------
// K4: shifted fp16 image planes with halo (vectorized 16B stores)
//     g_xsh[b][sh][ci][hp][w] = x[b][ci][hp-1][w+sh-1]  (0 outside)
// ---------------------------------------------------------------------------
__global__ void k_xsh(const float* __restrict__ x) {
    const int ci = blockIdx.x, sh = blockIdx.y, b = blockIdx.z;
    const float* xc = x + ((size_t)(b * IC + ci) << 12);
    __half* dst = g_xsh + ((((size_t)b * 3 + sh) * IC + ci) * 66) * 64;
    const int dx = sh - 1;
    for (int c = threadIdx.x; c < 66 * 8; c += 256) {
        const int hp = c >> 3, w0 = (c & 7) * 8;
        const int h = hp - 1;
        __half hv[8];
#pragma unroll
        for (int e = 0; e < 8; ++e) {
            const int ws = w0 + e + dx;
            float v = ((unsigned)h < 64u && (unsigned)ws < 64u)
                          ? __ldg(xc + (h << 6) + ws) : 0.f;
            hv[e] = __float2half_rn(v);
        }
        *(uint4*)(dst + hp * 64 + w0) = *(const uint4*)hv;
    }
}

// ---------------------------------------------------------------------------
// K5: GEMM, BK=32 stages (144 iters) to amortize barrier/ldsm/issue overhead.
// BM=128 x BN=256, 512 threads / 16 warps, 1 CTA/SM (2 CTAs/SM -> 64-reg cap
// -> catastrophic spills; do NOT re-attempt).
// A[4][128 rows x 144B]  (hi32|lo32|pad16B per row)
// B[4][32 k-rows x 264 halfs]
// Per thread per stage: 2 cp16 (A) + 2 cp16 (B).
// ---------------------------------------------------------------------------
#define A_ST   18432               // 128 * 144
#define B_ST   16896               // 32 * 528
#define B_OFF  73728               // 4 * A_ST
#define SMEM_TOTAL (B_OFF + 4 * B_ST)   // 141,312

__global__ void __launch_bounds__(512, 1)
k_gemm(const float* __restrict__ b_conv, float* __restrict__ out) {
    extern __shared__ char smem[];
    const uint32_t sb = (uint32_t)__cvta_generic_to_shared(smem);
    const int tid = threadIdx.x, wid = tid >> 5, lane = tid & 31;
    const int mt = blockIdx.x, nt = blockIdx.y, b = blockIdx.z;
    const int o0 = mt * 128, p0 = nt * 256;
    const int wm = (wid >> 2) * 32, wn = (wid & 3) * 64;

    // -------- A cp.async: 2 cp16/thread. chunk c=tid*2+{0,1}: row=c>>3,
    //          seg=c&7 -> plane=seg>>2, q=seg&3 --------
    const int arow = tid >> 2;
    const int sg0  = (tid & 3) * 2;          // even seg
    const int sg1  = sg0 + 1;
    const __half* aAsrc0 =
        ((sg0 >> 2) ? g_Alo : g_Ahi) + ((size_t)(b * OC + o0 + arow)) * KTOT + (sg0 & 3) * 8;
    const __half* aAsrc1 =
        ((sg1 >> 2) ? g_Alo : g_Ahi) + ((size_t)(b * OC + o0 + arow)) * KTOT + (sg1 & 3) * 8;
    const uint32_t aAdst0 = sb + (uint32_t)(arow * 144 + (sg0 >> 2) * 64 + (sg0 & 3) * 16);
    const uint32_t aAdst1 = sb + (uint32_t)(arow * 144 + (sg1 >> 2) * 64 + (sg1 & 3) * 16);

    auto issueA = [&](int s) {
        const int st = s & 3;
        cp16(aAdst0 + st * A_ST, aAsrc0 + s * 32);
        cp16(aAdst1 + st * A_ST, aAsrc1 + s * 32);
    };

    // -------- B cp.async: 2 cp16/thread (k-rows 2*wid, 2*wid+1; chunk=lane) --------
    const int kr0 = wid * 2, kr1 = kr0 + 1;
    const int lr  = lane >> 3;               // image row within N-tile
    const int seg = lane & 7;                // 8-half chunk within 64-px row
    const int r0  = p0 >> 6;
    const __half* xshb = g_xsh + ((size_t)b * 3 * IC) * 66 * 64;
    const uint32_t bdst0 = sb + B_OFF + (uint32_t)(kr0 * 528 + lane * 16);
    const uint32_t bdst1 = sb + B_OFF + (uint32_t)(kr1 * 528 + lane * 16);

    auto issueB = [&](int s) {
        const int st = s & 3;
        {
            const int k = s * 32 + kr0;
            const int ci = k / 9, t = k - ci * 9;
            const int ty = t / 3, tx = t - ty * 3;
            cp16(bdst0 + st * B_ST,
                 xshb + (((size_t)tx * IC + ci) * 66 + (r0 + lr + ty)) * 64 + seg * 8);
        }
        {
            const int k = s * 32 + kr1;
            const int ci = k / 9, t = k - ci * 9;
            const int ty = t / 3, tx = t - ty * 3;
            cp16(bdst1 + st * B_ST,
                 xshb + (((size_t)tx * IC + ci) * 66 + (r0 + lr + ty)) * 64 + seg * 8);
        }
    };

    // -------- ldmatrix lane offsets --------
    const uint32_t a_lane = (uint32_t)((lane & 15) * 144 + (lane >> 4) * 16);
    const uint32_t b_lane = (uint32_t)((((lane & 7) + ((lane >> 3) & 1) * 8) * 264 +
                                       ((lane >> 4) << 3)) * 2);

    float acc[2][8][4];
#pragma unroll
    for (int mi = 0; mi < 2; ++mi)
#pragma unroll
        for (int j = 0; j < 8; ++j)
#pragma unroll
            for (int q = 0; q < 4; ++q) acc[mi][j][q] = 0.f;

    issueA(0); issueB(0); cp_commit();
    issueA(1); issueB(1); cp_commit();
    issueA(2); issueB(2); cp_commit();

#pragma unroll 1
    for (int s = 0; s < NKS2; ++s) {
        cp_wait2();
        __syncthreads();
        if (s + 3 < NKS2) { issueA(s + 3); issueB(s + 3); }
        cp_commit();

        const uint32_t ab = sb + (s & 3) * A_ST;
        const uint32_t bb = sb + B_OFF + (s & 3) * B_ST;

        uint32_t ahi[2][2][4], alo[2][2][4];
#pragma unroll
        for (int mi = 0; mi < 2; ++mi) {
            const uint32_t ad = ab + (uint32_t)((wm + mi * 16) * 144) + a_lane;
#pragma unroll
            for (int f = 0; f < 2; ++f) {
                ldsm4(ahi[mi][f], ad + f * 32);
                ldsm4(alo[mi][f], ad + 64 + f * 32);
            }
        }
#pragma unroll
        for (int n2 = 0; n2 < 4; ++n2) {
#pragma unroll
            for (int f = 0; f < 2; ++f) {
                uint32_t bf[4];
                ldsm4t(bf, bb + (uint32_t)(f * 8448) +
                           (uint32_t)((wn + n2 * 16) * 2) + b_lane);
#pragma unroll
                for (int mi = 0; mi < 2; ++mi)
#pragma unroll
                    for (int nf = 0; nf < 2; ++nf) {
                        float* c = acc[mi][n2 * 2 + nf];
                        mma16816(c, ahi[mi][f], &bf[nf * 2]);
                        mma16816(c, alo[mi][f], &bf[nf * 2]);
                    }
            }
        }
    }

    // -------- epilogue: demodulate + bias --------
    const int row_l = lane >> 2, col_l = (lane & 3) * 2;
#pragma unroll
    for (int mi = 0; mi < 2; ++mi) {
        const int oa = o0 + wm + mi * 16 + row_l;
        const int ob = oa + 8;
        const float sa = g_sig[b * OC + oa], ba = b_conv[oa];
        const float sc = g_sig[b * OC + ob], bc = b_conv[ob];
        float* ra = out + (((size_t)(b * OC + oa)) << 12) + p0 + wn + col_l;
        float* rb = out + (((size_t)(b * OC + ob)) << 12) + p0 + wn + col_l;
#pragma unroll
        for (int j = 0; j < 8; ++j) {
            float2 v0, v1;
            v0.x = acc[mi][j][0] * sa + ba;
            v0.y = acc[mi][j][1] * sa + ba;
            v1.x = acc[mi][j][2] * sc + bc;
            v1.y = acc[mi][j][3] * sc + bc;
            *(float2*)(ra + j * 8) = v0;
            *(float2*)(rb + j * 8) = v1;
        }
    }
}

// ---------------------------------------------------------------------------
extern "C" void kernel_launch(void* const* d_in, const int* in_sizes, int n_in,
                              void* d_out, int out_size) {
    const float* x      = (const float*)d_in[0];
    const float* latent = (const float*)d_in[1];
    const float* w_lin  = (const float*)d_in[2];
    const float* b_lin  = (const float*)d_in[3];
    const float* w_conv = (const float*)d_in[4];
    const float* b_conv = (const float*)d_in[5];
    float* out = (float*)d_out;

    cudaFuncSetAttribute(k_gemm, cudaFuncAttributeMaxDynamicSharedMemorySize, SMEM_TOTAL);

    k_style<<<dim3(NB, 64), 256>>>(latent, w_lin, b_lin);
    k_sigma<<<OC, 128>>>(w_conv);
    k_moda<<<dim3(OC, NB), 256>>>(w_conv);
    k_xsh<<<dim3(IC, 3, NB), 256>>>(x);
    k_gemm<<<dim3(4, 16, NB), 512, SMEM_TOTAL>>>(b_conv, out);
}

// round 13
// speedup vs baseline: 4.9262x; 1.5328x over previous
#include <cuda_runtime.h>
#include <cuda_fp16.h>
#include <cstdint>

#define NB   8
#define IC   512
#define OC   512
#define PX   4096
#define KTOT 4608
#define NKS2 144           // KTOT / 32

// ---------------- scratch (device globals; no allocation) ----------------
__device__ float g_smod[NB * IC];
__device__ float g_s2[NB * IC];
__device__ float g_sig[NB * OC];
__device__ __half g_A[(size_t)NB * OC * KTOT];       // [b][o][k]  single fp16 plane
// shifted, halo-padded fp16 images: [b][shift 0..2][ci][h_pad 0..65][w 0..63]
__device__ __half g_xsh[(size_t)NB * 3 * IC * 66 * 64];

// ---------------- baseline-PTX helpers (valid on plain sm_103) ----------------
__device__ __forceinline__ void cp16(uint32_t dst, const void* src) {
    asm volatile("cp.async.cg.shared.global [%0], [%1], 16;" :: "r"(dst), "l"(src));
}
__device__ __forceinline__ void cp_commit() {
    asm volatile("cp.async.commit_group;" ::: "memory");
}
__device__ __forceinline__ void cp_wait2() {
    asm volatile("cp.async.wait_group 2;" ::: "memory");
}
__device__ __forceinline__ void ldsm4(uint32_t* r, uint32_t a) {
    asm volatile("ldmatrix.sync.aligned.m8n8.x4.shared.b16 {%0,%1,%2,%3}, [%4];"
                 : "=r"(r[0]), "=r"(r[1]), "=r"(r[2]), "=r"(r[3]) : "r"(a));
}
__device__ __forceinline__ void ldsm4t(uint32_t* r, uint32_t a) {
    asm volatile("ldmatrix.sync.aligned.m8n8.x4.trans.shared.b16 {%0,%1,%2,%3}, [%4];"
                 : "=r"(r[0]), "=r"(r[1]), "=r"(r[2]), "=r"(r[3]) : "r"(a));
}
__device__ __forceinline__ void mma16816(float* c, const uint32_t* a, const uint32_t* b) {
    asm volatile(
        "mma.sync.aligned.m16n8k16.row.col.f32.f16.f16.f32 "
        "{%0,%1,%2,%3},{%4,%5,%6,%7},{%8,%9},{%0,%1,%2,%3};"
        : "+f"(c[0]), "+f"(c[1]), "+f"(c[2]), "+f"(c[3])
        : "r"(a[0]), "r"(a[1]), "r"(a[2]), "r"(a[3]), "r"(b[0]), "r"(b[1]));
}

// ---------------------------------------------------------------------------
// K1: style  s[b,i] = latent.w_lin * C_LIN + b_lin   (warp per output i)
// ---------------------------------------------------------------------------
__global__ void k_style(const float* __restrict__ latent,
                        const float* __restrict__ w_lin,
                        const float* __restrict__ b_lin) {
    __shared__ float lat[512];
    const int b = blockIdx.x;
    const int tid = threadIdx.x, lane = tid & 31;
    lat[tid]       = latent[b * 512 + tid];
    lat[tid + 256] = latent[b * 512 + tid + 256];
    __syncthreads();
    const int i = blockIdx.y * 8 + (tid >> 5);
    const float4* wr = (const float4*)(w_lin + (size_t)i * 512);
    float acc = 0.f;
#pragma unroll
    for (int t = 0; t < 4; ++t) {
        float4 v = __ldg(wr + lane + t * 32);
        int j0 = (lane + t * 32) * 4;
        acc += v.x * lat[j0] + v.y * lat[j0 + 1] + v.z * lat[j0 + 2] + v.w * lat[j0 + 3];
    }
#pragma unroll
    for (int st = 16; st > 0; st >>= 1) acc += __shfl_xor_sync(0xffffffffu, acc, st);
    if (lane == 0) {
        const float C_LIN  = 0.04419417382415922f;   // 1/sqrt(512)
        const float C_CONV = 0.014731391274719742f;  // 1/sqrt(4608)
        float s = acc * C_LIN + b_lin[i];
        g_smod[b * 512 + i] = s * C_CONV;
        g_s2[b * 512 + i]   = s * s;
    }
}

// ---------------------------------------------------------------------------
// K2: sigma_inv[b,o]
// ---------------------------------------------------------------------------
__global__ void k_sigma(const float* __restrict__ w_conv) {
    __shared__ float red[8][128];
    const int o = blockIdx.x;
    const int tid = threadIdx.x;
    float acc[8];
#pragma unroll
    for (int b = 0; b < 8; ++b) acc[b] = 0.f;
    for (int i = tid; i < 512; i += 128) {
        const float* wp = w_conv + ((size_t)o * 512 + i) * 9;
        float ws = 0.f;
#pragma unroll
        for (int t = 0; t < 9; ++t) { float v = wp[t]; ws += v * v; }
#pragma unroll
        for (int b = 0; b < 8; ++b) acc[b] += ws * g_s2[b * 512 + i];
    }
#pragma unroll
    for (int b = 0; b < 8; ++b) red[b][tid] = acc[b];
    __syncthreads();
    for (int st = 64; st > 0; st >>= 1) {
        if (tid < st) {
#pragma unroll
            for (int b = 0; b < 8; ++b) red[b][tid] += red[b][tid + st];
        }
        __syncthreads();
    }
    if (tid < 8) {
        const float C2 = 1.0f / 4608.0f;
        g_sig[tid * 512 + o] = rsqrtf(red[tid][0] * C2 + 1e-8f);
    }
}

// ---------------------------------------------------------------------------
// K3: modulated weights -> single fp16 plane  [b][o][k]  (16B stores)
// ---------------------------------------------------------------------------
__global__ void k_moda(const float* __restrict__ w_conv) {
    const int o = blockIdx.x, b = blockIdx.y;
    const float* wr = w_conv + (size_t)o * KTOT;
    const float* sm = g_smod + b * IC;
    __half* ah = g_A + ((size_t)(b * OC + o)) * KTOT;
    for (int g = threadIdx.x; g < KTOT / 8; g += 256) {
        const int k0 = g * 8;
        __half hv[8];
#pragma unroll
        for (int e = 0; e < 8; ++e) {
            int k = k0 + e;
            hv[e] = __float2half_rn(__ldg(wr + k) * sm[k / 9]);
        }
        *(uint4*)(ah + k0) = *(const uint4*)hv;
    }
}

// ---------------------------------------------------------------------------
// K4: shifted fp16 image planes with halo (vectorized 16B stores)
//     g_xsh[b][sh][ci][hp][w] = x[b][ci][hp-1][w+sh-1]  (0 outside)
// ---------------------------------------------------------------------------
__global__ void k_xsh(const float* __restrict__ x) {
    const int ci = blockIdx.x, sh = blockIdx.y, b = blockIdx.z;
    const float* xc = x + ((size_t)(b * IC + ci) << 12);
    __half* dst = g_xsh + ((((size_t)b * 3 + sh) * IC + ci) * 66) * 64;
    const int dx = sh - 1;
    for (int c = threadIdx.x; c < 66 * 8; c += 256) {
        const int hp = c >> 3, w0 = (c & 7) * 8;
        const int h = hp - 1;
        __half hv[8];
#pragma unroll
        for (int e = 0; e < 8; ++e) {
            const int ws = w0 + e + dx;
            float v = ((unsigned)h < 64u && (unsigned)ws < 64u)
                          ? __ldg(xc + (h << 6) + ws) : 0.f;
            hv[e] = __float2half_rn(v);
        }
        *(uint4*)(dst + hp * 64 + w0) = *(const uint4*)hv;
    }
}

// ---------------------------------------------------------------------------
// K5: single-term fp16 GEMM, BK=32 stages (144 iters).
// BM=128 x BN=256, 512 threads / 16 warps, 1 CTA/SM (2 CTAs/SM -> 64-reg cap
// -> catastrophic spills; do NOT re-attempt).
// A[4][128 rows x 80B]  (32 halfs + 16B pad per row; odd 16B multiple)
// B[4][32 k-rows x 264 halfs]
// Per thread per stage: 1 cp16 (A) + 2 cp16 (B).
// ---------------------------------------------------------------------------
#define A_ST   10240               // 128 * 80
#define B_ST   16896               // 32 * 528
#define B_OFF  40960               // 4 * A_ST
#define SMEM_TOTAL (B_OFF + 4 * B_ST)   // 108,544

__global__ void __launch_bounds__(512, 1)
k_gemm(const float* __restrict__ b_conv, float* __restrict__ out) {
    extern __shared__ char smem[];
    const uint32_t sb = (uint32_t)__cvta_generic_to_shared(smem);
    const int tid = threadIdx.x, wid = tid >> 5, lane = tid & 31;
    const int mt = blockIdx.x, nt = blockIdx.y, b = blockIdx.z;
    const int o0 = mt * 128, p0 = nt * 256;
    const int wm = (wid >> 2) * 32, wn = (wid & 3) * 64;

    // -------- A cp.async: 1 cp16/thread (128 rows x 4 chunks of 16B) --------
    const int arow = tid >> 2, aseg = tid & 3;
    const __half* asrc = g_A + ((size_t)(b * OC + o0 + arow)) * KTOT + aseg * 8;
    const uint32_t adst = sb + (uint32_t)(arow * 80 + aseg * 16);

    auto issueA = [&](int s) {
        cp16(adst + (s & 3) * A_ST, asrc + s * 32);
    };

    // -------- B cp.async: 2 cp16/thread (k-rows 2*wid, 2*wid+1; chunk=lane) --------
    const int kr0 = wid * 2, kr1 = kr0 + 1;
    const int lr  = lane >> 3;               // image row within N-tile
    const int seg = lane & 7;                // 8-half chunk within 64-px row
    const int r0  = p0 >> 6;
    const __half* xshb = g_xsh + ((size_t)b * 3 * IC) * 66 * 64;
    const uint32_t bdst0 = sb + B_OFF + (uint32_t)(kr0 * 528 + lane * 16);
    const uint32_t bdst1 = sb + B_OFF + (uint32_t)(kr1 * 528 + lane * 16);

    auto issueB = [&](int s) {
        const int st = s & 3;
        {
            const int k = s * 32 + kr0;
            const int ci = k / 9, t = k - ci * 9;
            const int ty = t / 3, tx = t - ty * 3;
            cp16(bdst0 + st * B_ST,
                 xshb + (((size_t)tx * IC + ci) * 66 + (r0 + lr + ty)) * 64 + seg * 8);
        }
        {
            const int k = s * 32 + kr1;
            const int ci = k / 9, t = k - ci * 9;
            const int ty = t / 3, tx = t - ty * 3;
            cp16(bdst1 + st * B_ST,
                 xshb + (((size_t)tx * IC + ci) * 66 + (r0 + lr + ty)) * 64 + seg * 8);
        }
    };

    // -------- ldmatrix lane offsets --------
    const uint32_t a_lane = (uint32_t)((lane & 15) * 80 + (lane >> 4) * 16);
    const uint32_t b_lane = (uint32_t)((((lane & 7) + ((lane >> 3) & 1) * 8) * 264 +
                                       ((lane >> 4) << 3)) * 2);

    float acc[2][8][4];
#pragma unroll
    for (int mi = 0; mi < 2; ++mi)
#pragma unroll
        for (int j = 0; j < 8; ++j)
#pragma unroll
            for (int q = 0; q < 4; ++q) acc[mi][j][q] = 0.f;

    issueA(0); issueB(0); cp_commit();
    issueA(1); issueB(1); cp_commit();
    issueA(2); issueB(2); cp_commit();

#pragma unroll 1
    for (int s = 0; s < NKS2; ++s) {
        cp_wait2();
        __syncthreads();
        if (s + 3 < NKS2) { issueA(s + 3); issueB(s + 3); }
        cp_commit();

        const uint32_t ab = sb + (s & 3) * A_ST;
        const uint32_t bb = sb + B_OFF + (s & 3) * B_ST;

        uint32_t af[2][2][4];                 // [mi][f(k16)]
#pragma unroll
        for (int mi = 0; mi < 2; ++mi) {
            const uint32_t ad = ab + (uint32_t)((wm + mi * 16) * 80) + a_lane;
            ldsm4(af[mi][0], ad);
            ldsm4(af[mi][1], ad + 32);
        }
#pragma unroll
        for (int n2 = 0; n2 < 4; ++n2) {
#pragma unroll
            for (int f = 0; f < 2; ++f) {
                uint32_t bf[4];
                ldsm4t(bf, bb + (uint32_t)(f * 8448) +
                           (uint32_t)((wn + n2 * 16) * 2) + b_lane);
#pragma unroll
                for (int mi = 0; mi < 2; ++mi)
#pragma unroll
                    for (int nf = 0; nf < 2; ++nf)
                        mma16816(acc[mi][n2 * 2 + nf], af[mi][f], &bf[nf * 2]);
            }
        }
    }

    // -------- epilogue: demodulate + bias --------
    const int row_l = lane >> 2, col_l = (lane & 3) * 2;
#pragma unroll
    for (int mi = 0; mi < 2; ++mi) {
        const int oa = o0 + wm + mi * 16 + row_l;
        const int ob = oa + 8;
        const float sa = g_sig[b * OC + oa], ba = b_conv[oa];
        const float sc = g_sig[b * OC + ob], bc = b_conv[ob];
        float* ra = out + (((size_t)(b * OC + oa)) << 12) + p0 + wn + col_l;
        float* rb = out + (((size_t)(b * OC + ob)) << 12) + p0 + wn + col_l;
#pragma unroll
        for (int j = 0; j < 8; ++j) {
            float2 v0, v1;
            v0.x = acc[mi][j][0] * sa + ba;
            v0.y = acc[mi][j][1] * sa + ba;
            v1.x = acc[mi][j][2] * sc + bc;
            v1.y = acc[mi][j][3] * sc + bc;
            *(float2*)(ra + j * 8) = v0;
            *(float2*)(rb + j * 8) = v1;
        }
    }
}

// ---------------------------------------------------------------------------
extern "C" void kernel_launch(void* const* d_in, const int* in_sizes, int n_in,
                              void* d_out, int out_size) {
    const float* x      = (const float*)d_in[0];
    const float* latent = (const float*)d_in[1];
    const float* w_lin  = (const float*)d_in[2];
    const float* b_lin  = (const float*)d_in[3];
    const float* w_conv = (const float*)d_in[4];
    const float* b_conv = (const float*)d_in[5];
    float* out = (float*)d_out;

    cudaFuncSetAttribute(k_gemm, cudaFuncAttributeMaxDynamicSharedMemorySize, SMEM_TOTAL);

    k_style<<<dim3(NB, 64), 256>>>(latent, w_lin, b_lin);
    k_sigma<<<OC, 128>>>(w_conv);
    k_moda<<<dim3(OC, NB), 256>>>(w_conv);
    k_xsh<<<dim3(IC, 3, NB), 256>>>(x);
    k_gemm<<<dim3(4, 16, NB), 512, SMEM_TOTAL>>>(b_conv, out);
}

// round 14
// speedup vs baseline: 6.1329x; 1.2449x over previous
#include <cuda_runtime.h>
#include <cuda_fp16.h>
#include <cstdint>

#define NB   8
#define IC   512
#define OC   512
#define PX   4096
#define KTOT 4608
#define NKS2 144           // KTOT / 32

// ---------------- scratch (device globals; no allocation) ----------------
__device__ float g_smod[NB * IC];
__device__ float g_s2[NB * IC];
__device__ float g_sig[NB * OC];
__device__ __half g_A[(size_t)NB * OC * KTOT];       // [b][o][k]  single fp16 plane
// shifted, halo-padded fp16 images: [b][shift 0..2][ci][h_pad 0..65][w 0..63]
__device__ __half g_xsh[(size_t)NB * 3 * IC * 66 * 64];

// ---------------- baseline-PTX helpers (valid on plain sm_103) ----------------
__device__ __forceinline__ void cp16(uint32_t dst, const void* src) {
    asm volatile("cp.async.cg.shared.global [%0], [%1], 16;" :: "r"(dst), "l"(src));
}
__device__ __forceinline__ void cp_commit() {
    asm volatile("cp.async.commit_group;" ::: "memory");
}
__device__ __forceinline__ void cp_wait2() {
    asm volatile("cp.async.wait_group 2;" ::: "memory");
}
__device__ __forceinline__ void ldsm4(uint32_t* r, uint32_t a) {
    asm volatile("ldmatrix.sync.aligned.m8n8.x4.shared.b16 {%0,%1,%2,%3}, [%4];"
                 : "=r"(r[0]), "=r"(r[1]), "=r"(r[2]), "=r"(r[3]) : "r"(a));
}
__device__ __forceinline__ void ldsm4t(uint32_t* r, uint32_t a) {
    asm volatile("ldmatrix.sync.aligned.m8n8.x4.trans.shared.b16 {%0,%1,%2,%3}, [%4];"
                 : "=r"(r[0]), "=r"(r[1]), "=r"(r[2]), "=r"(r[3]) : "r"(a));
}
__device__ __forceinline__ void mma16816(float* c, const uint32_t* a, const uint32_t* b) {
    asm volatile(
        "mma.sync.aligned.m16n8k16.row.col.f32.f16.f16.f32 "
        "{%0,%1,%2,%3},{%4,%5,%6,%7},{%8,%9},{%0,%1,%2,%3};"
        : "+f"(c[0]), "+f"(c[1]), "+f"(c[2]), "+f"(c[3])
        : "r"(a[0]), "r"(a[1]), "r"(a[2]), "r"(a[3]), "r"(b[0]), "r"(b[1]));
}

// ---------------------------------------------------------------------------
// K1: style  s[b,i] = latent.w_lin * C_LIN + b_lin   (warp per output i)
// ---------------------------------------------------------------------------
__global__ void k_style(const float* __restrict__ latent,
                        const float* __restrict__ w_lin,
                        const float* __restrict__ b_lin) {
    __shared__ float lat[512];
    const int b = blockIdx.x;
    const int tid = threadIdx.x, lane = tid & 31;
    lat[tid]       = latent[b * 512 + tid];
    lat[tid + 256] = latent[b * 512 + tid + 256];
    __syncthreads();
    const int i = blockIdx.y * 8 + (tid >> 5);
    const float4* wr = (const float4*)(w_lin + (size_t)i * 512);
    float acc = 0.f;
#pragma unroll
    for (int t = 0; t < 4; ++t) {
        float4 v = __ldg(wr + lane + t * 32);
        int j0 = (lane + t * 32) * 4;
        acc += v.x * lat[j0] + v.y * lat[j0 + 1] + v.z * lat[j0 + 2] + v.w * lat[j0 + 3];
    }
#pragma unroll
    for (int st = 16; st > 0; st >>= 1) acc += __shfl_xor_sync(0xffffffffu, acc, st);
    if (lane == 0) {
        const float C_LIN  = 0.04419417382415922f;   // 1/sqrt(512)
        const float C_CONV = 0.014731391274719742f;  // 1/sqrt(4608)
        float s = acc * C_LIN + b_lin[i];
        g_smod[b * 512 + i] = s * C_CONV;
        g_s2[b * 512 + i]   = s * s;
    }
}

// ---------------------------------------------------------------------------
// K2: fused modulate + sigma.  Per (o,b): write A fp16 plane and
// sigma_inv[b,o] = rsqrt( (sum_k w[k]^2 * s2[i(k)]) / 4608 + eps )
// ---------------------------------------------------------------------------
__global__ void k_moda(const float* __restrict__ w_conv) {
    __shared__ float red[256];
    const int o = blockIdx.x, b = blockIdx.y, tid = threadIdx.x;
    const float* wr = w_conv + (size_t)o * KTOT;
    const float* sm = g_smod + b * IC;
    const float* s2 = g_s2 + b * IC;
    __half* ah = g_A + ((size_t)(b * OC + o)) * KTOT;
    float accs = 0.f;
    for (int g = tid; g < KTOT / 8; g += 256) {
        const int k0 = g * 8;
        __half hv[8];
#pragma unroll
        for (int e = 0; e < 8; ++e) {
            int k = k0 + e;
            int i = k / 9;
            float w = __ldg(wr + k);
            hv[e] = __float2half_rn(w * sm[i]);
            accs += w * w * s2[i];
        }
        *(uint4*)(ah + k0) = *(const uint4*)hv;
    }
    red[tid] = accs;
    __syncthreads();
    for (int st = 128; st > 0; st >>= 1) {
        if (tid < st) red[tid] += red[tid + st];
        __syncthreads();
    }
    if (tid == 0)
        g_sig[b * OC + o] = rsqrtf(red[0] * (1.0f / 4608.0f) + 1e-8f);
}

// ---------------------------------------------------------------------------
// K3: shifted fp16 planes, one block per (ci,b): read x once into a haloed
// smem tile, emit all 3 shifts with uint4 stores.
// ---------------------------------------------------------------------------
__global__ void k_xsh(const float* __restrict__ x) {
    __shared__ float tile[66][68];    // rows hp 0..65 (h=hp-1), cols wc 0..65 (w=wc-1)
    const int ci = blockIdx.x, b = blockIdx.y, tid = threadIdx.x;
    const float* xc = x + ((size_t)(b * IC + ci) << 12);
    // zero whole tile (66*68 floats, float2 strides)
    for (int i = tid; i < 66 * 34; i += 256)
        *(float2*)(&tile[0][0] + i * 2) = make_float2(0.f, 0.f);
    __syncthreads();
    // interior: rows 1..64, cols 1..64
    for (int i = tid; i < 64 * 16; i += 256) {
        const int r = i >> 4, c4 = (i & 15) * 4;
        float4 v = *(const float4*)(xc + (r << 6) + c4);
        tile[r + 1][c4 + 1] = v.x;
        tile[r + 1][c4 + 2] = v.y;
        tile[r + 1][c4 + 3] = v.z;
        tile[r + 1][c4 + 4] = v.w;
    }
    __syncthreads();
    // emit: 3 shifts x 66 rows x 8 chunks of 8 halfs
    __half* dst0 = g_xsh + (((size_t)b * 3) * IC + ci) * 66 * 64;
    for (int i = tid; i < 3 * 66 * 8; i += 256) {
        const int sh = i / 528;
        const int rem = i - sh * 528;
        const int hp = rem >> 3, c8 = (rem & 7) * 8;
        __half hv[8];
#pragma unroll
        for (int e = 0; e < 8; ++e)
            hv[e] = __float2half_rn(tile[hp][c8 + e + sh]);
        *(uint4*)(dst0 + ((size_t)sh * IC * 66 + hp) * 64 + c8) = *(const uint4*)hv;
    }
}

// ---------------------------------------------------------------------------
// K4: fp16 GEMM, BM=128 x BN=128, BK=32 stages, 256 threads / 8 warps,
// __launch_bounds__(256, 2): reg cap = 65536/512 = 128 (matches natural ~120;
// the R7 disaster was 512 threads -> 64-reg cap. 512-thr + occ2 stays banned).
// 1024 tiles on 296 slots -> smoother wave quantization + cross-CTA overlap.
// A[4][128 rows x 80B] (32 halfs + 16B pad); B[4][32 k-rows x 272B] (128h+pad)
// Per thread per stage: 2 cp16 (A) + 2 cp16 (B).
// ---------------------------------------------------------------------------
#define A_ST   10240               // 128 * 80
#define B_ST   8704                // 32 * 272
#define B_OFF  40960               // 4 * A_ST
#define SMEM_TOTAL (B_OFF + 4 * B_ST)   // 75,776

__global__ void __launch_bounds__(256, 2)
k_gemm(const float* __restrict__ b_conv, float* __restrict__ out) {
    extern __shared__ char smem[];
    const uint32_t sb = (uint32_t)__cvta_generic_to_shared(smem);
    const int tid = threadIdx.x, wid = tid >> 5, lane = tid & 31;
    const int mt = blockIdx.x, nt = blockIdx.y, b = blockIdx.z;
    const int o0 = mt * 128, p0 = nt * 128;
    const int wm = (wid >> 1) * 32, wn = (wid & 1) * 64;

    // -------- A cp.async: 2 cp16/thread (row = tid>>1, chunks 2t, 2t+1) --------
    const int arow = tid >> 1, ac0 = (tid & 1) * 2;
    const __half* asrc = g_A + ((size_t)(b * OC + o0 + arow)) * KTOT + ac0 * 8;
    const uint32_t adst = sb + (uint32_t)(arow * 80 + ac0 * 16);

    auto issueA = [&](int s) {
        const uint32_t d = adst + (s & 3) * A_ST;
        cp16(d, asrc + s * 32);
        cp16(d + 16, asrc + s * 32 + 8);
    };

    // -------- B cp.async: 2 cp16/thread (k-row = tid>>3; image rows 0,1) ------
    const int kr  = tid >> 3;                // 0..31
    const int seg = tid & 7;                 // 8-half chunk within 64-px row
    const int r0  = nt * 2;                  // base image row of this N-tile
    const __half* xshb = g_xsh + ((size_t)b * 3 * IC) * 66 * 64;
    const uint32_t bdst = sb + B_OFF + (uint32_t)(kr * 272 + seg * 16);

    auto issueB = [&](int s) {
        const int k = s * 32 + kr;
        const int ci = k / 9, t = k - ci * 9;
        const int ty = t / 3, tx = t - ty * 3;
        const __half* src =
            xshb + (((size_t)tx * IC + ci) * 66 + (r0 + ty)) * 64 + seg * 8;
        const uint32_t d = bdst + (s & 3) * B_ST;
        cp16(d, src);                        // image row 0
        cp16(d + 128, src + 64);             // image row 1
    };

    // -------- ldmatrix lane offsets --------
    const uint32_t a_lane = (uint32_t)((lane & 15) * 80 + (lane >> 4) * 16);
    const uint32_t b_lane = (uint32_t)((((lane & 7) + ((lane >> 3) & 1) * 8) * 136 +
                                       ((lane >> 4) << 3)) * 2);

    float acc[2][8][4];
#pragma unroll
    for (int mi = 0; mi < 2; ++mi)
#pragma unroll
        for (int j = 0; j < 8; ++j)
#pragma unroll
            for (int q = 0; q < 4; ++q) acc[mi][j][q] = 0.f;

    issueA(0); issueB(0); cp_commit();
    issueA(1); issueB(1); cp_commit();
    issueA(2); issueB(2); cp_commit();

#pragma unroll 1
    for (int s = 0; s < NKS2; ++s) {
        cp_wait2();
        __syncthreads();
        if (s + 3 < NKS2) { issueA(s + 3); issueB(s + 3); }
        cp_commit();

        const uint32_t ab = sb + (s & 3) * A_ST;
        const uint32_t bb = sb + B_OFF + (s & 3) * B_ST;

        uint32_t af[2][2][4];                 // [mi][f(k16)]
#pragma unroll
        for (int mi = 0; mi < 2; ++mi) {
            const uint32_t ad = ab + (uint32_t)((wm + mi * 16) * 80) + a_lane;
            ldsm4(af[mi][0], ad);
            ldsm4(af[mi][1], ad + 32);
        }
#pragma unroll
        for (int n2 = 0; n2 < 4; ++n2) {
#pragma unroll
            for (int f = 0; f < 2; ++f) {
                uint32_t bf[4];
                ldsm4t(bf, bb + (uint32_t)(f * 4352) +
                           (uint32_t)((wn + n2 * 16) * 2) + b_lane);
#pragma unroll
                for (int mi = 0; mi < 2; ++mi)
#pragma unroll
                    for (int nf = 0; nf < 2; ++nf)
                        mma16816(acc[mi][n2 * 2 + nf], af[mi][f], &bf[nf * 2]);
            }
        }
    }

    // -------- epilogue: demodulate + bias --------
    const int row_l = lane >> 2, col_l = (lane & 3) * 2;
#pragma unroll
    for (int mi = 0; mi < 2; ++mi) {
        const int oa = o0 + wm + mi * 16 + row_l;
        const int ob = oa + 8;
        const float sa = g_sig[b * OC + oa], ba = b_conv[oa];
        const float sc = g_sig[b * OC + ob], bc = b_conv[ob];
        float* ra = out + (((size_t)(b * OC + oa)) << 12) + p0 + wn + col_l;
        float* rb = out + (((size_t)(b * OC + ob)) << 12) + p0 + wn + col_l;
#pragma unroll
        for (int j = 0; j < 8; ++j) {
            float2 v0, v1;
            v0.x = acc[mi][j][0] * sa + ba;
            v0.y = acc[mi][j][1] * sa + ba;
            v1.x = acc[mi][j][2] * sc + bc;
            v1.y = acc[mi][j][3] * sc + bc;
            *(float2*)(ra + j * 8) = v0;
            *(float2*)(rb + j * 8) = v1;
        }
    }
}

// ---------------------------------------------------------------------------
extern "C" void kernel_launch(void* const* d_in, const int* in_sizes, int n_in,
                              void* d_out, int out_size) {
    const float* x      = (const float*)d_in[0];
    const float* latent = (const float*)d_in[1];
    const float* w_lin  = (const float*)d_in[2];
    const float* b_lin  = (const float*)d_in[3];
    const float* w_conv = (const float*)d_in[4];
    const float* b_conv = (const float*)d_in[5];
    float* out = (float*)d_out;

    cudaFuncSetAttribute(k_gemm, cudaFuncAttributeMaxDynamicSharedMemorySize, SMEM_TOTAL);

    k_style<<<dim3(NB, 64), 256>>>(latent, w_lin, b_lin);
    k_moda<<<dim3(OC, NB), 256>>>(w_conv);
    k_xsh<<<dim3(IC, NB), 256>>>(x);
    k_gemm<<<dim3(4, 32, NB), 256, SMEM_TOTAL>>>(b_conv, out);
}

// round 15
// speedup vs baseline: 6.2745x; 1.0231x over previous
#include <cuda_runtime.h>
#include <cuda_fp16.h>
#include <cstdint>

#define NB   8
#define IC   512
#define OC   512
#define PX   4096
#define KTOT 4608
#define NKS2 144           // KTOT / 32
#define STG  5             // pipeline depth

// ---------------- scratch (device globals; no allocation) ----------------
__device__ float g_smod[NB * IC];
__device__ float g_s2[NB * IC];
__device__ float g_sig[NB * OC];
__device__ __half g_A[(size_t)NB * OC * KTOT];       // [b][o][k]  single fp16 plane
// shifted, halo-padded fp16 images: [b][shift 0..2][ci][h_pad 0..65][w 0..63]
__device__ __half g_xsh[(size_t)NB * 3 * IC * 66 * 64];

// ---------------- baseline-PTX helpers (valid on plain sm_103) ----------------
__device__ __forceinline__ void cp16(uint32_t dst, const void* src) {
    asm volatile("cp.async.cg.shared.global [%0], [%1], 16;" :: "r"(dst), "l"(src));
}
__device__ __forceinline__ void cp_commit() {
    asm volatile("cp.async.commit_group;" ::: "memory");
}
__device__ __forceinline__ void cp_wait3() {
    asm volatile("cp.async.wait_group 3;" ::: "memory");
}
__device__ __forceinline__ void ldsm4(uint32_t* r, uint32_t a) {
    asm volatile("ldmatrix.sync.aligned.m8n8.x4.shared.b16 {%0,%1,%2,%3}, [%4];"
                 : "=r"(r[0]), "=r"(r[1]), "=r"(r[2]), "=r"(r[3]) : "r"(a));
}
__device__ __forceinline__ void ldsm4t(uint32_t* r, uint32_t a) {
    asm volatile("ldmatrix.sync.aligned.m8n8.x4.trans.shared.b16 {%0,%1,%2,%3}, [%4];"
                 : "=r"(r[0]), "=r"(r[1]), "=r"(r[2]), "=r"(r[3]) : "r"(a));
}
__device__ __forceinline__ void mma16816(float* c, const uint32_t* a, const uint32_t* b) {
    asm volatile(
        "mma.sync.aligned.m16n8k16.row.col.f32.f16.f16.f32 "
        "{%0,%1,%2,%3},{%4,%5,%6,%7},{%8,%9},{%0,%1,%2,%3};"
        : "+f"(c[0]), "+f"(c[1]), "+f"(c[2]), "+f"(c[3])
        : "r"(a[0]), "r"(a[1]), "r"(a[2]), "r"(a[3]), "r"(b[0]), "r"(b[1]));
}

// ---------------------------------------------------------------------------
// K1: style  s[b,i] = latent.w_lin * C_LIN + b_lin   (warp per output i)
// ---------------------------------------------------------------------------
__global__ void k_style(const float* __restrict__ latent,
                        const float* __restrict__ w_lin,
                        const float* __restrict__ b_lin) {
    __shared__ float lat[512];
    const int b = blockIdx.x;
    const int tid = threadIdx.x, lane = tid & 31;
    lat[tid]       = latent[b * 512 + tid];
    lat[tid + 256] = latent[b * 512 + tid + 256];
    __syncthreads();
    const int i = blockIdx.y * 8 + (tid >> 5);
    const float4* wr = (const float4*)(w_lin + (size_t)i * 512);
    float acc = 0.f;
#pragma unroll
    for (int t = 0; t < 4; ++t) {
        float4 v = __ldg(wr + lane + t * 32);
        int j0 = (lane + t * 32) * 4;
        acc += v.x * lat[j0] + v.y * lat[j0 + 1] + v.z * lat[j0 + 2] + v.w * lat[j0 + 3];
    }
#pragma unroll
    for (int st = 16; st > 0; st >>= 1) acc += __shfl_xor_sync(0xffffffffu, acc, st);
    if (lane == 0) {
        const float C_LIN  = 0.04419417382415922f;   // 1/sqrt(512)
        const float C_CONV = 0.014731391274719742f;  // 1/sqrt(4608)
        float s = acc * C_LIN + b_lin[i];
        g_smod[b * 512 + i] = s * C_CONV;
        g_s2[b * 512 + i]   = s * s;
    }
}

// ---------------------------------------------------------------------------
// K2: fused modulate + sigma, single pass over w_conv (read once, emit 8 b).
// ---------------------------------------------------------------------------
__global__ void k_moda(const float* __restrict__ w_conv) {
    __shared__ float red[8][8];
    const int o = blockIdx.x, tid = threadIdx.x;
    const int lane = tid & 31, wrp = tid >> 5;
    const float* wr = w_conv + (size_t)o * KTOT;
    float accs[8];
#pragma unroll
    for (int b = 0; b < 8; ++b) accs[b] = 0.f;

    for (int g = tid; g < KTOT / 8; g += 256) {
        const int k0 = g * 8;
        float w[8];
        float4 w0 = __ldg((const float4*)(wr + k0));
        float4 w1 = __ldg((const float4*)(wr + k0 + 4));
        w[0] = w0.x; w[1] = w0.y; w[2] = w0.z; w[3] = w0.w;
        w[4] = w1.x; w[5] = w1.y; w[6] = w1.z; w[7] = w1.w;
        __half hv[8][8];                       // [b][e]
#pragma unroll
        for (int e = 0; e < 8; ++e) {
            const int i = (k0 + e) / 9;
            const float w2 = w[e] * w[e];
#pragma unroll
            for (int b = 0; b < 8; ++b) {
                hv[b][e] = __float2half_rn(w[e] * g_smod[b * 512 + i]);
                accs[b] += w2 * g_s2[b * 512 + i];
            }
        }
#pragma unroll
        for (int b = 0; b < 8; ++b)
            *(uint4*)(g_A + ((size_t)(b * OC + o)) * KTOT + k0) = *(const uint4*)hv[b];
    }
#pragma unroll
    for (int st = 16; st > 0; st >>= 1)
#pragma unroll
        for (int b = 0; b < 8; ++b)
            accs[b] += __shfl_xor_sync(0xffffffffu, accs[b], st);
    if (lane == 0)
#pragma unroll
        for (int b = 0; b < 8; ++b) red[b][wrp] = accs[b];
    __syncthreads();
    if (tid < 8) {
        float v = 0.f;
#pragma unroll
        for (int w8 = 0; w8 < 8; ++w8) v += red[tid][w8];
        g_sig[tid * 512 + o] = rsqrtf(v * (1.0f / 4608.0f) + 1e-8f);
    }
}

// ---------------------------------------------------------------------------
// K3: shifted fp16 planes, one block per (ci,b): read x once into a haloed
// smem tile, emit all 3 shifts with uint4 stores.
// ---------------------------------------------------------------------------
__global__ void k_xsh(const float* __restrict__ x) {
    __shared__ float tile[66][68];
    const int ci = blockIdx.x, b = blockIdx.y, tid = threadIdx.x;
    const float* xc = x + ((size_t)(b * IC + ci) << 12);
    for (int i = tid; i < 66 * 34; i += 256)
        *(float2*)(&tile[0][0] + i * 2) = make_float2(0.f, 0.f);
    __syncthreads();
    for (int i = tid; i < 64 * 16; i += 256) {
        const int r = i >> 4, c4 = (i & 15) * 4;
        float4 v = *(const float4*)(xc + (r << 6) + c4);
        tile[r + 1][c4 + 1] = v.x;
        tile[r + 1][c4 + 2] = v.y;
        tile[r + 1][c4 + 3] = v.z;
        tile[r + 1][c4 + 4] = v.w;
    }
    __syncthreads();
    __half* dst0 = g_xsh + (((size_t)b * 3) * IC + ci) * 66 * 64;
    for (int i = tid; i < 3 * 66 * 8; i += 256) {
        const int sh = i / 528;
        const int rem = i - sh * 528;
        const int hp = rem >> 3, c8 = (rem & 7) * 8;
        __half hv[8];
#pragma unroll
        for (int e = 0; e < 8; ++e)
            hv[e] = __float2half_rn(tile[hp][c8 + e + sh]);
        *(uint4*)(dst0 + ((size_t)sh * IC * 66 + hp) * 64 + c8) = *(const uint4*)hv;
    }
}

// ---------------------------------------------------------------------------
// K4: fp16 GEMM, BM=128 x BN=128, BK=32, 5-stage cp.async pipeline,
// 256 threads / 8 warps, __launch_bounds__(256,2) (reg cap 128 = natural use;
// 512-thr + occ2 -> 64-reg cap catastrophic spills: stays banned).
// A[5][128 rows x 80B]; B[5][32 k-rows x 272B].  wait_group 3 per stage.
// ---------------------------------------------------------------------------
#define A_ST   10240               // 128 * 80
#define B_ST   8704                // 32 * 272
#define B_OFF  (STG * A_ST)        // 51,200
#define SMEM_TOTAL (B_OFF + STG * B_ST)   // 94,720

__global__ void __launch_bounds__(256, 2)
k_gemm(const float* __restrict__ b_conv, float* __restrict__ out) {
    extern __shared__ char smem[];
    const uint32_t sb = (uint32_t)__cvta_generic_to_shared(smem);
    const int tid = threadIdx.x, wid = tid >> 5, lane = tid & 31;
    const int mt = blockIdx.x, nt = blockIdx.y, b = blockIdx.z;
    const int o0 = mt * 128, p0 = nt * 128;
    const int wm = (wid >> 1) * 32, wn = (wid & 1) * 64;

    // -------- A cp.async: 2 cp16/thread --------
    const int arow = tid >> 1, ac0 = (tid & 1) * 2;
    const __half* asrc = g_A + ((size_t)(b * OC + o0 + arow)) * KTOT + ac0 * 8;
    const uint32_t adst = sb + (uint32_t)(arow * 80 + ac0 * 16);

    auto issueA = [&](int s, int buf) {
        const uint32_t d = adst + buf * A_ST;
        cp16(d, asrc + s * 32);
        cp16(d + 16, asrc + s * 32 + 8);
    };

    // -------- B cp.async: 2 cp16/thread --------
    const int kr  = tid >> 3;
    const int seg = tid & 7;
    const int r0  = nt * 2;
    const __half* xshb = g_xsh + ((size_t)b * 3 * IC) * 66 * 64;
    const uint32_t bdst = sb + B_OFF + (uint32_t)(kr * 272 + seg * 16);

    auto issueB = [&](int s, int buf) {
        const int k = s * 32 + kr;
        const int ci = k / 9, t = k - ci * 9;
        const int ty = t / 3, tx = t - ty * 3;
        const __half* src =
            xshb + (((size_t)tx * IC + ci) * 66 + (r0 + ty)) * 64 + seg * 8;
        const uint32_t d = bdst + buf * B_ST;
        cp16(d, src);
        cp16(d + 128, src + 64);
    };

    // -------- ldmatrix lane offsets --------
    const uint32_t a_lane = (uint32_t)((lane & 15) * 80 + (lane >> 4) * 16);
    const uint32_t b_lane = (uint32_t)((((lane & 7) + ((lane >> 3) & 1) * 8) * 136 +
                                       ((lane >> 4) << 3)) * 2);

    float acc[2][8][4];
#pragma unroll
    for (int mi = 0; mi < 2; ++mi)
#pragma unroll
        for (int j = 0; j < 8; ++j)
#pragma unroll
            for (int q = 0; q < 4; ++q) acc[mi][j][q] = 0.f;

    issueA(0, 0); issueB(0, 0); cp_commit();
    issueA(1, 1); issueB(1, 1); cp_commit();
    issueA(2, 2); issueB(2, 2); cp_commit();
    issueA(3, 3); issueB(3, 3); cp_commit();

    int ibuf = 4, cbuf = 0;
#pragma unroll 1
    for (int s = 0; s < NKS2; ++s) {
        cp_wait3();
        __syncthreads();
        if (s + 4 < NKS2) { issueA(s + 4, ibuf); issueB(s + 4, ibuf); }
        cp_commit();
        if (++ibuf == STG) ibuf = 0;

        const uint32_t ab = sb + cbuf * A_ST;
        const uint32_t bb = sb + B_OFF + cbuf * B_ST;
        if (++cbuf == STG) cbuf = 0;

        uint32_t af[2][2][4];                 // [mi][f(k16)]
#pragma unroll
        for (int mi = 0; mi < 2; ++mi) {
            const uint32_t ad = ab + (uint32_t)((wm + mi * 16) * 80) + a_lane;
            ldsm4(af[mi][0], ad);
            ldsm4(af[mi][1], ad + 32);
        }
#pragma unroll
        for (int n2 = 0; n2 < 4; ++n2) {
#pragma unroll
            for (int f = 0; f < 2; ++f) {
                uint32_t bf[4];
                ldsm4t(bf, bb + (uint32_t)(f * 4352) +
                           (uint32_t)((wn + n2 * 16) * 2) + b_lane);
#pragma unroll
                for (int mi = 0; mi < 2; ++mi)
#pragma unroll
                    for (int nf = 0; nf < 2; ++nf)
                        mma16816(acc[mi][n2 * 2 + nf], af[mi][f], &bf[nf * 2]);
            }
        }
    }

    // -------- epilogue: demodulate + bias --------
    const int row_l = lane >> 2, col_l = (lane & 3) * 2;
#pragma unroll
    for (int mi = 0; mi < 2; ++mi) {
        const int oa = o0 + wm + mi * 16 + row_l;
        const int ob = oa + 8;
        const float sa = g_sig[b * OC + oa], ba = b_conv[oa];
        const float sc = g_sig[b * OC + ob], bc = b_conv[ob];
        float* ra = out + (((size_t)(b * OC + oa)) << 12) + p0 + wn + col_l;
        float* rb = out + (((size_t)(b * OC + ob)) << 12) + p0 + wn + col_l;
#pragma unroll
        for (int j = 0; j < 8; ++j) {
            float2 v0, v1;
            v0.x = acc[mi][j][0] * sa + ba;
            v0.y = acc[mi][j][1] * sa + ba;
            v1.x = acc[mi][j][2] * sc + bc;
            v1.y = acc[mi][j][3] * sc + bc;
            *(float2*)(ra + j * 8) = v0;
            *(float2*)(rb + j * 8) = v1;
        }
    }
}

// ---------------------------------------------------------------------------
extern "C" void kernel_launch(void* const* d_in, const int* in_sizes, int n_in,
                              void* d_out, int out_size) {
    const float* x      = (const float*)d_in[0];
    const float* latent = (const float*)d_in[1];
    const float* w_lin  = (const float*)d_in[2];
    const float* b_lin  = (const float*)d_in[3];
    const float* w_conv = (const float*)d_in[4];
    const float* b_conv = (const float*)d_in[5];
    float* out = (float*)d_out;

    cudaFuncSetAttribute(k_gemm, cudaFuncAttributeMaxDynamicSharedMemorySize, SMEM_TOTAL);

    k_style<<<dim3(NB, 64), 256>>>(latent, w_lin, b_lin);
    k_moda<<<OC, 256>>>(w_conv);
    k_xsh<<<dim3(IC, NB), 256>>>(x);
    k_gemm<<<dim3(4, 32, NB), 256, SMEM_TOTAL>>>(b_conv, out);
}